// round 7
// baseline (speedup 1.0000x reference)
#include <cuda_runtime.h>
#include <cstdint>

// Problem constants
#define B_   4
#define T_   1024
#define E_   512
#define H_   8
#define L_   4
#define V_   32000
#define HID_ 100
#define HD_  64
#define BT_  (B_*T_)

// ---------------- scratch (no allocations allowed) ----------------
__device__ float g_x[BT_*E_];
__device__ float g_h[BT_*E_];
__device__ float g_q[BT_*E_];
__device__ float g_k[BT_*E_];
__device__ float g_v[BT_*E_];
__device__ float g_y[BT_*E_];
__device__ float g_m[BT_*HID_];
__device__ float g_wr[4*L_*E_*E_];     // rounded Wq|Wk|Wv|Wo
__device__ float g_wlm[E_*V_];         // rounded Wlm

// ---------------- tf32 helpers ----------------
__device__ __forceinline__ uint32_t f2tf(float f) {
    uint32_t r;
    asm("cvt.rna.tf32.f32 %0, %1;" : "=r"(r) : "f"(f));
    return r;
}
__device__ __forceinline__ float rndtf(float f) { return __uint_as_float(f2tf(f)); }

__device__ __forceinline__ void mma_tf32(float* c, const uint32_t* a, const uint32_t* b) {
    asm volatile(
      "mma.sync.aligned.m16n8k8.row.col.f32.tf32.tf32.f32 "
      "{%0,%1,%2,%3}, {%4,%5,%6,%7}, {%8,%9}, {%0,%1,%2,%3};\n"
      : "+f"(c[0]), "+f"(c[1]), "+f"(c[2]), "+f"(c[3])
      : "r"(a[0]), "r"(a[1]), "r"(a[2]), "r"(a[3]), "r"(b[0]), "r"(b[1]));
}

#define CP16(su32, gptr) \
    asm volatile("cp.async.ca.shared.global [%0], [%1], 16;" :: "r"(su32), "l"(gptr) : "memory")
#define CP_COMMIT() asm volatile("cp.async.commit_group;" ::: "memory")
#define CP_WAIT2()  asm volatile("cp.async.wait_group 2;"  ::: "memory")

// ---------------- block reductions ----------------
__device__ __forceinline__ float blockReduceSum(float v) {
    __shared__ float sh[32];
    int lane = threadIdx.x & 31, w = threadIdx.x >> 5;
    #pragma unroll
    for (int o = 16; o > 0; o >>= 1) v += __shfl_xor_sync(0xffffffffu, v, o);
    if (lane == 0) sh[w] = v;
    __syncthreads();
    v = (threadIdx.x < (blockDim.x >> 5)) ? sh[threadIdx.x] : 0.f;
    if (w == 0) {
        #pragma unroll
        for (int o = 16; o > 0; o >>= 1) v += __shfl_xor_sync(0xffffffffu, v, o);
        if (lane == 0) sh[0] = v;
    }
    __syncthreads();
    float r = sh[0];
    __syncthreads();
    return r;
}

__device__ __forceinline__ float blockReduceMax(float v) {
    __shared__ float sh[32];
    int lane = threadIdx.x & 31, w = threadIdx.x >> 5;
    #pragma unroll
    for (int o = 16; o > 0; o >>= 1) v = fmaxf(v, __shfl_xor_sync(0xffffffffu, v, o));
    if (lane == 0) sh[w] = v;
    __syncthreads();
    v = (threadIdx.x < (blockDim.x >> 5)) ? sh[threadIdx.x] : -1e30f;
    if (w == 0) {
        #pragma unroll
        for (int o = 16; o > 0; o >>= 1) v = fmaxf(v, __shfl_xor_sync(0xffffffffu, v, o));
        if (lane == 0) sh[0] = v;
    }
    __syncthreads();
    float r = sh[0];
    __syncthreads();
    return r;
}

// ---------------- elementwise tf32 rounding (pre-pass) ----------------
__global__ void round_k(const float* __restrict__ src, float* __restrict__ dst, int n4) {
    int i = blockIdx.x * 256 + threadIdx.x;
    if (i >= n4) return;
    float4 v = ((const float4*)src)[i];
    v.x = rndtf(v.x); v.y = rndtf(v.y); v.z = rndtf(v.z); v.w = rndtf(v.w);
    ((float4*)dst)[i] = v;
}

// ---------------- embedding ----------------
__global__ void embed_k(const int* __restrict__ idx, const float* __restrict__ tok,
                        const float* __restrict__ pos, float* __restrict__ x) {
    int i = blockIdx.x * 256 + threadIdx.x;
    if (i >= BT_*E_) return;
    int e  = i & (E_-1);
    int bt = i >> 9;
    int t  = bt & (T_-1);
    x[i] = tok[(long long)idx[bt]*E_ + e] + pos[t*E_ + e];
}

// ---------------- layernorm (rounded tf32 output) ----------------
__global__ void layernorm_k(const float* __restrict__ x, const float* __restrict__ g,
                            const float* __restrict__ bb, float* __restrict__ out) {
    const float* xr = x + (long long)blockIdx.x * E_;
    float v0 = xr[threadIdx.x], v1 = xr[threadIdx.x + 256];
    float mean = blockReduceSum(v0 + v1) * (1.f / E_);
    float d0 = v0 - mean, d1 = v1 - mean;
    float var = blockReduceSum(d0*d0 + d1*d1) * (1.f / E_);
    float rstd = rsqrtf(var + 1e-5f);
    float* o = out + (long long)blockIdx.x * E_;
    o[threadIdx.x]       = rndtf(d0 * rstd * g[threadIdx.x]       + bb[threadIdx.x]);
    o[threadIdx.x + 256] = rndtf(d1 * rstd * g[threadIdx.x + 256] + bb[threadIdx.x + 256]);
}

// ---------------- causal softmax, in-place ----------------
__global__ void softmax_causal_k(float* __restrict__ attn) {
    long long z = blockIdx.y;
    int t = blockIdx.x;
    float* row = attn + z * (long long)(T_*T_) + (long long)t * T_;
    int len = t + 1;
    float mx = -1e30f;
    for (int s = threadIdx.x; s < len; s += 256) mx = fmaxf(mx, row[s]);
    mx = blockReduceMax(mx);
    float sum = 0.f;
    for (int s = threadIdx.x; s < len; s += 256) sum += expf(row[s] - mx);
    sum = blockReduceSum(sum);
    float inv = 1.f / sum;
    for (int s = threadIdx.x; s < len; s += 256) row[s] = expf(row[s] - mx) * inv;
    for (int s = len + threadIdx.x; s < T_; s += 256) row[s] = 0.f;
}

// ============================================================================
// TF32 tensor-core GEMM, cp.async 4-stage pipeline, pre-rounded inputs.
// 128x128 tile, BK=16, 8 warps each 64x32 via mma.m16n8k8.
// Dynamic smem: 4 stages x (A 128x20 + B region 2560 words) = 81920 bytes.
// A natural padded [row][20]; B: !TRANSB [k][136], TRANSB natural [n][20].
// ============================================================================
#define AW 20
#define BW 136
#define STAGE_W 5120
#define SMEM_TF32_BYTES (4*STAGE_W*4)

template<bool TRANSB, bool HASBIAS, bool HASRES, bool ROUND>
__device__ __forceinline__
void gemm_tf32_body(const float* __restrict__ A, const float* __restrict__ Bm,
                    float* __restrict__ C,
                    int K, int lda, int ldb, int ldc,
                    const float* __restrict__ bias,
                    const float* __restrict__ resid,
                    float alpha, int row0, int col0) {
    extern __shared__ float dsm[];

    const int tid  = threadIdx.x;
    const int lane = tid & 31;
    const int wid  = tid >> 5;
    const int warpM = wid >> 2;          // 0..1
    const int warpN = wid & 3;           // 0..3
    const int g    = lane >> 2;
    const int tg   = lane & 3;

    // staging addressing
    const int ar = tid >> 1, ac = (tid & 1) * 8;     // 128-row tiles (A, TRANSB-B)
    const int bk = tid >> 4, bn = (tid & 15) * 8;    // !TRANSB B: k-row, n-offset

    const float* Ag = A + (long long)(row0 + ar) * lda + ac;
    const float* Bg = TRANSB ? (Bm + (long long)(col0 + ar) * ldb + ac)
                             : (Bm + (long long)bk * ldb + col0 + bn);

    const uint32_t sA = (uint32_t)__cvta_generic_to_shared(dsm) + (ar * AW + ac) * 4;
    const uint32_t sB = (uint32_t)__cvta_generic_to_shared(dsm) + 2560 * 4 +
                        (TRANSB ? (ar * AW + ac) * 4 : (bk * BW + bn) * 4);

    const int KT = K >> 4;

    // issue stage kt into slot
    auto issue = [&](int kt, int slot) {
        const uint32_t off = slot * (STAGE_W * 4);
        const float* ga = Ag + kt * 16;
        CP16(sA + off, ga);
        CP16(sA + off + 16, ga + 4);
        if (TRANSB) {
            const float* gb = Bg + kt * 16;
            CP16(sB + off, gb);
            CP16(sB + off + 16, gb + 4);
        } else {
            const float* gb = Bg + (long long)kt * 16 * ldb;
            CP16(sB + off, gb);
            CP16(sB + off + 16, gb + 4);
        }
    };

    float acc[4][4][4];
    #pragma unroll
    for (int i = 0; i < 4; i++)
        #pragma unroll
        for (int j = 0; j < 4; j++)
            #pragma unroll
            for (int r = 0; r < 4; r++) acc[i][j][r] = 0.f;

    // prologue: 3 stages ahead
    #pragma unroll
    for (int i = 0; i < 3; i++) {
        if (i < KT) issue(i, i);
        CP_COMMIT();
    }

    for (int kt = 0; kt < KT; kt++) {
        CP_WAIT2();
        __syncthreads();

        const int nx = kt + 3;
        if (nx < KT) issue(nx, nx & 3);
        CP_COMMIT();

        const float* As = dsm + (kt & 3) * STAGE_W;
        const float* Bs = As + 2560;

        #pragma unroll
        for (int ks = 0; ks < 2; ks++) {
            const int kk = ks * 8 + tg;
            uint32_t af[4][4];
            #pragma unroll
            for (int im = 0; im < 4; im++) {
                const int r = warpM * 64 + im * 16 + g;
                af[im][0] = __float_as_uint(As[r * AW + kk]);
                af[im][1] = __float_as_uint(As[(r + 8) * AW + kk]);
                af[im][2] = __float_as_uint(As[r * AW + kk + 4]);
                af[im][3] = __float_as_uint(As[(r + 8) * AW + kk + 4]);
            }
            uint32_t bf[4][2];
            #pragma unroll
            for (int in = 0; in < 4; in++) {
                const int c = warpN * 32 + in * 8 + g;
                if (!TRANSB) {
                    bf[in][0] = __float_as_uint(Bs[kk * BW + c]);
                    bf[in][1] = __float_as_uint(Bs[(kk + 4) * BW + c]);
                } else {
                    bf[in][0] = __float_as_uint(Bs[c * AW + kk]);
                    bf[in][1] = __float_as_uint(Bs[c * AW + kk + 4]);
                }
            }
            #pragma unroll
            for (int im = 0; im < 4; im++)
                #pragma unroll
                for (int in = 0; in < 4; in++)
                    mma_tf32(acc[im][in], af[im], bf[in]);
        }
        __syncthreads();
    }

    // ---- epilogue ----
    #pragma unroll
    for (int im = 0; im < 4; im++) {
        #pragma unroll
        for (int half = 0; half < 2; half++) {
            const int gm = row0 + warpM * 64 + im * 16 + g + half * 8;
            float* crow = C + (long long)gm * ldc;
            const float* rrow = HASRES ? (resid + (long long)gm * ldc) : nullptr;
            #pragma unroll
            for (int in = 0; in < 4; in++) {
                const int gn = col0 + warpN * 32 + in * 8 + tg * 2;
                float2 v;
                v.x = acc[im][in][half * 2 + 0] * alpha;
                v.y = acc[im][in][half * 2 + 1] * alpha;
                if (HASBIAS) {
                    v.x += bias[gn];
                    v.y += bias[gn + 1];
                }
                if (HASRES) {
                    float2 rr = *(const float2*)(rrow + gn);
                    v.x += rr.x; v.y += rr.y;
                }
                if (ROUND) { v.x = rndtf(v.x); v.y = rndtf(v.y); }
                *(float2*)(crow + gn) = v;
            }
        }
    }
}

// generic batched entry
template<bool TRANSB, bool HASBIAS, bool HASRES, bool CAUSAL, bool ROUND>
__global__ __launch_bounds__(256, 2)
void gemm_tf32_k(const float* __restrict__ A, const float* __restrict__ Bm,
                 float* __restrict__ C,
                 int K, int lda, int ldb, int ldc,
                 int innerCnt,
                 long long soA, long long siA,
                 long long soB, long long siB,
                 long long soC, long long siC,
                 const float* __restrict__ bias,
                 const float* __restrict__ resid,
                 float alpha) {
    const int row0 = blockIdx.y * 128;
    const int col0 = blockIdx.x * 128;
    if (CAUSAL && col0 > row0 + 127) return;
    int bz = blockIdx.z;
    int zo = bz / innerCnt;
    int zi = bz - zo * innerCnt;
    A  += zo * soA + zi * siA;
    Bm += zo * soB + zi * siB;
    C  += zo * soC + zi * siC;
    if (HASRES) resid += zo * soC + zi * siC;
    gemm_tf32_body<TRANSB, HASBIAS, HASRES, ROUND>(A, Bm, C, K, lda, ldb, ldc,
                                                   bias, resid, alpha, row0, col0);
}

// fused QKV: blockIdx.z selects (W, out); outputs rounded to tf32
__global__ __launch_bounds__(256, 2)
void gemm_tf32_qkv_k(const float* __restrict__ A,
                     const float* __restrict__ W0, const float* __restrict__ W1,
                     const float* __restrict__ W2,
                     float* __restrict__ C0, float* __restrict__ C1,
                     float* __restrict__ C2) {
    const int row0 = blockIdx.y * 128;
    const int col0 = blockIdx.x * 128;
    const float* Bm = (blockIdx.z == 0) ? W0 : (blockIdx.z == 1) ? W1 : W2;
    float* C = (blockIdx.z == 0) ? C0 : (blockIdx.z == 1) ? C1 : C2;
    gemm_tf32_body<false, false, false, true>(A, Bm, C, E_, E_, E_, E_,
                                              nullptr, nullptr, 1.f, row0, col0);
}

// ---------------- generic batched SGEMM (small/odd shapes) ----------------
#define BM 64
#define BN 64
#define BKK 16

template<bool TRANSB, bool RELU, bool HASBIAS, bool HASRES, bool CAUSAL, bool CAUSALK, bool RND>
__global__ __launch_bounds__(256)
void gemm_k(const float* __restrict__ A, const float* __restrict__ Bm,
            float* __restrict__ C,
            int M, int N, int K, int lda, int ldb, int ldc,
            int innerCnt,
            long long soA, long long siA,
            long long soB, long long siB,
            long long soC, long long siC,
            const float* __restrict__ bias,
            const float* __restrict__ resid,
            float alpha) {
    int row0 = blockIdx.y * BM;
    int col0 = blockIdx.x * BN;
    if (CAUSAL) {
        if (col0 > row0 + BM - 1) return;
    }
    int bz = blockIdx.z;
    int zo = bz / innerCnt;
    int zi = bz - zo * innerCnt;
    A  += zo * soA + zi * siA;
    Bm += zo * soB + zi * siB;
    C  += zo * soC + zi * siC;
    const float* R = resid;
    if (HASRES) R += zo * soC + zi * siC;

    __shared__ float As[BKK][BM];
    __shared__ float Bs[BKK][BN + 4];

    int tid = threadIdx.x;
    int tx = tid & 15;
    int ty = tid >> 4;
    float acc[4][4] = {};

    int Kend = K;
    if (CAUSALK) { int ke = row0 + BM; Kend = ke < K ? ke : K; }

    for (int k0 = 0; k0 < Kend; k0 += BKK) {
        #pragma unroll
        for (int i = 0; i < 4; i++) {
            int li = tid * 4 + i;
            int m = li >> 4, k = li & 15;
            int gm = row0 + m, gk = k0 + k;
            float v = 0.f;
            if (gm < M && gk < K) v = A[(long long)gm * lda + gk];
            As[k][m] = v;
        }
        if (!TRANSB) {
            #pragma unroll
            for (int i = 0; i < 4; i++) {
                int li = tid * 4 + i;
                int k = li >> 6, n = li & 63;
                int gk = k0 + k, gn = col0 + n;
                float v = 0.f;
                if (gk < K && gn < N) v = Bm[(long long)gk * ldb + gn];
                Bs[k][n] = v;
            }
        } else {
            #pragma unroll
            for (int i = 0; i < 4; i++) {
                int li = tid * 4 + i;
                int n = li >> 4, k = li & 15;
                int gn = col0 + n, gk = k0 + k;
                float v = 0.f;
                if (gn < N && gk < K) v = Bm[(long long)gn * ldb + gk];
                Bs[k][n] = v;
            }
        }
        __syncthreads();
        #pragma unroll
        for (int k = 0; k < BKK; k++) {
            float4 a4 = *(const float4*)&As[k][ty * 4];
            float4 b4 = *(const float4*)&Bs[k][tx * 4];
            float a[4] = {a4.x, a4.y, a4.z, a4.w};
            float b[4] = {b4.x, b4.y, b4.z, b4.w};
            #pragma unroll
            for (int i = 0; i < 4; i++)
                #pragma unroll
                for (int j = 0; j < 4; j++)
                    acc[i][j] = fmaf(a[i], b[j], acc[i][j]);
        }
        __syncthreads();
    }

    #pragma unroll
    for (int i = 0; i < 4; i++) {
        int gm = row0 + ty * 4 + i;
        if (gm >= M) continue;
        #pragma unroll
        for (int j = 0; j < 4; j++) {
            int gn = col0 + tx * 4 + j;
            if (gn >= N) continue;
            float v = acc[i][j] * alpha;
            if (HASBIAS) v += bias[gn];
            if (HASRES)  v += R[(long long)gm * ldc + gn];
            if (RELU)    v = fmaxf(v, 0.f);
            if (RND)     v = rndtf(v);
            C[(long long)gm * ldc + gn] = v;
        }
    }
}

// ---------------- host launcher ----------------
extern "C" void kernel_launch(void* const* d_in, const int* in_sizes, int n_in,
                              void* d_out, int out_size) {
    const int*   idx   = (const int*)  d_in[0];
    const float* tok   = (const float*)d_in[1];
    const float* pos   = (const float*)d_in[2];
    const float* ln1_g = (const float*)d_in[3];
    const float* ln1_b = (const float*)d_in[4];
    const float* Wq    = (const float*)d_in[5];
    const float* Wk    = (const float*)d_in[6];
    const float* Wv    = (const float*)d_in[7];
    const float* Wo    = (const float*)d_in[8];
    const float* bo    = (const float*)d_in[9];
    const float* ln2_g = (const float*)d_in[10];
    const float* ln2_b = (const float*)d_in[11];
    const float* W1    = (const float*)d_in[12];
    const float* b1    = (const float*)d_in[13];
    const float* W2    = (const float*)d_in[14];
    const float* b2    = (const float*)d_in[15];
    const float* lnf_g = (const float*)d_in[16];
    const float* lnf_b = (const float*)d_in[17];
    const float* Wlm   = (const float*)d_in[18];

    float* out    = (float*)d_out;
    float* logits = out;                                  // (B,T,V)
    float* attn   = out + (long long)B_*T_*V_;            // (L,B,H,T,T)
    const long long ATTN1 = (long long)B_*H_*T_*T_;

    float *x, *h, *q, *k, *v, *y, *m, *wr, *wlm;
    cudaGetSymbolAddress((void**)&x, g_x);
    cudaGetSymbolAddress((void**)&h, g_h);
    cudaGetSymbolAddress((void**)&q, g_q);
    cudaGetSymbolAddress((void**)&k, g_k);
    cudaGetSymbolAddress((void**)&v, g_v);
    cudaGetSymbolAddress((void**)&y, g_y);
    cudaGetSymbolAddress((void**)&m, g_m);
    cudaGetSymbolAddress((void**)&wr, g_wr);
    cudaGetSymbolAddress((void**)&wlm, g_wlm);

    // opt-in dynamic smem for tf32 kernels (idempotent)
    cudaFuncSetAttribute(gemm_tf32_qkv_k,
        cudaFuncAttributeMaxDynamicSharedMemorySize, SMEM_TF32_BYTES);
    cudaFuncSetAttribute(gemm_tf32_k<true,false,false,true,false>,
        cudaFuncAttributeMaxDynamicSharedMemorySize, SMEM_TF32_BYTES);
    cudaFuncSetAttribute(gemm_tf32_k<false,true,true,false,false>,
        cudaFuncAttributeMaxDynamicSharedMemorySize, SMEM_TF32_BYTES);
    cudaFuncSetAttribute(gemm_tf32_k<false,false,false,false,false>,
        cudaFuncAttributeMaxDynamicSharedMemorySize, SMEM_TF32_BYTES);

    const long long WSZ = (long long)L_*E_*E_;
    float* wq = wr;            // rounded weights
    float* wk2 = wr + WSZ;
    float* wv = wr + 2*WSZ;
    float* wo = wr + 3*WSZ;

    // pre-pass: round weights to tf32 grid
    {
        int n4 = (int)(WSZ / 4);
        round_k<<<(n4 + 255)/256, 256>>>(Wq, wq, n4);
        round_k<<<(n4 + 255)/256, 256>>>(Wk, wk2, n4);
        round_k<<<(n4 + 255)/256, 256>>>(Wv, wv, n4);
        round_k<<<(n4 + 255)/256, 256>>>(Wo, wo, n4);
        int nlm4 = (E_*V_) / 4;
        round_k<<<(nlm4 + 255)/256, 256>>>(Wlm, wlm, nlm4);
    }

    // embedding
    {
        int n = BT_*E_;
        embed_k<<<(n + 255) / 256, 256>>>(idx, tok, pos, x);
    }

    dim3 gE(E_ / 128, BT_ / 128);               // (4, 32)    proj
    dim3 gQKV(E_ / 128, BT_ / 128, 3);          // (4, 32, 3) fused QKV
    dim3 gLM(V_ / 128, BT_ / 128);              // (250, 32)  lm head
    dim3 gS(T_ / 128, T_ / 128, B_*H_);         // (8, 8, 32) scores
    dim3 gAV(1, T_ / 64, B_*H_);                // (1, 16,32) attn @ V
    dim3 gM1((HID_ + 63) / 64, BT_ / 64);       // (2, 64)    mlp1
    const float scale = 0.125f;                 // 1/sqrt(64)

    for (int l = 0; l < L_; l++) {
        float* attnL = attn + (long long)l * ATTN1;

        layernorm_k<<<BT_, 256>>>(x, ln1_g + l*E_, ln1_b + l*E_, h);

        // q/k/v = h @ W   (fused, outputs tf32-rounded)
        gemm_tf32_qkv_k<<<gQKV, 256, SMEM_TF32_BYTES>>>(
            h, wq + (long long)l*E_*E_, wk2 + (long long)l*E_*E_,
            wv + (long long)l*E_*E_, q, k, v);

        // scores = scale * Q @ K^T
        gemm_tf32_k<true,false,false,true,false><<<gS, 256, SMEM_TF32_BYTES>>>(
            q, k, attnL, HD_, E_, E_, T_,
            H_,
            (long long)T_*E_, (long long)HD_,
            (long long)T_*E_, (long long)HD_,
            (long long)H_*T_*T_, (long long)T_*T_,
            nullptr, nullptr, scale);

        softmax_causal_k<<<dim3(T_, B_*H_), 256>>>(attnL);

        // y = P @ V  (fp32, causal-K bound; output tf32-rounded for proj)
        gemm_k<false,false,false,false,false,true,true><<<gAV, 256>>>(
            attnL, v, y, T_, HD_, T_, T_, E_, E_,
            H_,
            (long long)H_*T_*T_, (long long)T_*T_,
            (long long)T_*E_, (long long)HD_,
            (long long)T_*E_, (long long)HD_,
            nullptr, nullptr, 1.f);

        // x = x + y @ Wo + bo
        gemm_tf32_k<false,true,true,false,false><<<gE, 256, SMEM_TF32_BYTES>>>(
            y, wo + (long long)l*E_*E_, x, E_, E_, E_, E_,
            1, 0,0, 0,0, 0,0, bo + l*E_, x, 1.f);

        layernorm_k<<<BT_, 256>>>(x, ln2_g + l*E_, ln2_b + l*E_, h);

        // m = relu(h @ W1 + b1)
        gemm_k<false,true,true,false,false,false,false><<<gM1, 256>>>(
            h, W1 + (long long)l*E_*HID_, m, BT_, HID_, E_, E_, HID_, HID_,
            1, 0,0, 0,0, 0,0, b1 + l*HID_, nullptr, 1.f);

        // x = x + m @ W2 + b2
        gemm_k<false,false,true,true,false,false,false><<<dim3(E_/64, BT_/64), 256>>>(
            m, W2 + (long long)l*HID_*E_, x, BT_, E_, HID_, HID_, E_, E_,
            1, 0,0, 0,0, 0,0, b2 + l*E_, x, 1.f);
    }

    // final LN + LM head
    layernorm_k<<<BT_, 256>>>(x, lnf_g, lnf_b, h);
    gemm_tf32_k<false,false,false,false,false><<<gLM, 256, SMEM_TF32_BYTES>>>(
        h, wlm, logits, E_, E_, V_, V_,
        1, 0,0, 0,0, 0,0, nullptr, nullptr, 1.f);
}

// round 11
// speedup vs baseline: 1.1855x; 1.1855x over previous
#include <cuda_runtime.h>
#include <cuda_fp16.h>
#include <cstdint>

// Problem constants
#define B_   4
#define T_   1024
#define E_   512
#define H_   8
#define L_   4
#define V_   32000
#define HID_ 100
#define HD_  64
#define BT_  (B_*T_)

// ---------------- scratch (no allocations allowed) ----------------
__device__ float  g_x[BT_*E_];
__device__ float  g_h[BT_*E_];          // ln2 output (fp32, MLP path)
__device__ __half g_hh[BT_*E_];         // ln1/lnf output (half, GEMM path)
__device__ __half g_qh[BT_*E_];
__device__ __half g_kh[BT_*E_];
__device__ __half g_vh[BT_*E_];
__device__ __half g_yh[BT_*E_];
__device__ float  g_m[BT_*HID_];
__device__ __half g_wh[4*L_*E_*E_];     // transposed half Wq|Wk|Wv|Wo  ([N][K])
__device__ __half g_wlmh[(size_t)V_*E_]; // transposed half Wlm ([V][E])

// ---------------- helpers ----------------
__device__ __forceinline__ float ld_as_float(const float* p)  { return *p; }
__device__ __forceinline__ float ld_as_float(const __half* p) { return __half2float(*p); }
__device__ __forceinline__ void st_from_float(float* p, float v)  { *p = v; }
__device__ __forceinline__ void st_from_float(__half* p, float v) { *p = __float2half_rn(v); }

__device__ __forceinline__ void mma_f16(float* c, const uint32_t* a, const uint32_t* b) {
    asm volatile(
      "mma.sync.aligned.m16n8k16.row.col.f32.f16.f16.f32 "
      "{%0,%1,%2,%3}, {%4,%5,%6,%7}, {%8,%9}, {%0,%1,%2,%3};\n"
      : "+f"(c[0]), "+f"(c[1]), "+f"(c[2]), "+f"(c[3])
      : "r"(a[0]), "r"(a[1]), "r"(a[2]), "r"(a[3]), "r"(b[0]), "r"(b[1]));
}

#define CP16(su32, gptr) \
    asm volatile("cp.async.ca.shared.global [%0], [%1], 16;" :: "r"(su32), "l"(gptr) : "memory")
#define CP_COMMIT() asm volatile("cp.async.commit_group;" ::: "memory")
#define CP_WAIT2()  asm volatile("cp.async.wait_group 2;"  ::: "memory")

// ---------------- block reductions ----------------
__device__ __forceinline__ float blockReduceSum(float v) {
    __shared__ float sh[32];
    int lane = threadIdx.x & 31, w = threadIdx.x >> 5;
    #pragma unroll
    for (int o = 16; o > 0; o >>= 1) v += __shfl_xor_sync(0xffffffffu, v, o);
    if (lane == 0) sh[w] = v;
    __syncthreads();
    v = (threadIdx.x < (blockDim.x >> 5)) ? sh[threadIdx.x] : 0.f;
    if (w == 0) {
        #pragma unroll
        for (int o = 16; o > 0; o >>= 1) v += __shfl_xor_sync(0xffffffffu, v, o);
        if (lane == 0) sh[0] = v;
    }
    __syncthreads();
    float r = sh[0];
    __syncthreads();
    return r;
}

__device__ __forceinline__ float blockReduceMax(float v) {
    __shared__ float sh[32];
    int lane = threadIdx.x & 31, w = threadIdx.x >> 5;
    #pragma unroll
    for (int o = 16; o > 0; o >>= 1) v = fmaxf(v, __shfl_xor_sync(0xffffffffu, v, o));
    if (lane == 0) sh[w] = v;
    __syncthreads();
    v = (threadIdx.x < (blockDim.x >> 5)) ? sh[threadIdx.x] : -1e30f;
    if (w == 0) {
        #pragma unroll
        for (int o = 16; o > 0; o >>= 1) v = fmaxf(v, __shfl_xor_sync(0xffffffffu, v, o));
        if (lane == 0) sh[0] = v;
    }
    __syncthreads();
    float r = sh[0];
    __syncthreads();
    return r;
}

// ---------------- transpose + convert to half: src[R][C] f32 -> dst[C][R] half ----------------
__global__ void transpose_half_k(const float* __restrict__ src, __half* __restrict__ dst,
                                 int R, int Cc) {
    __shared__ float tile[32][33];
    int c0 = blockIdx.x * 32, r0 = blockIdx.y * 32;
    int tx = threadIdx.x & 31, ty = threadIdx.x >> 5;   // 256 threads, ty 0..7
    #pragma unroll
    for (int i = ty; i < 32; i += 8)
        tile[i][tx] = src[(long long)(r0 + i) * Cc + c0 + tx];
    __syncthreads();
    #pragma unroll
    for (int i = ty; i < 32; i += 8)
        dst[(long long)(c0 + i) * R + r0 + tx] = __float2half_rn(tile[tx][i]);
}

// ---------------- embedding ----------------
__global__ void embed_k(const int* __restrict__ idx, const float* __restrict__ tok,
                        const float* __restrict__ pos, float* __restrict__ x) {
    int i = blockIdx.x * 256 + threadIdx.x;
    if (i >= BT_*E_) return;
    int e  = i & (E_-1);
    int bt = i >> 9;
    int t  = bt & (T_-1);
    x[i] = tok[(long long)idx[bt]*E_ + e] + pos[t*E_ + e];
}

// ---------------- layernorm: fp32 out / half out ----------------
__global__ void layernorm_f_k(const float* __restrict__ x, const float* __restrict__ g,
                              const float* __restrict__ bb, float* __restrict__ out) {
    const float* xr = x + (long long)blockIdx.x * E_;
    float v0 = xr[threadIdx.x], v1 = xr[threadIdx.x + 256];
    float mean = blockReduceSum(v0 + v1) * (1.f / E_);
    float d0 = v0 - mean, d1 = v1 - mean;
    float var = blockReduceSum(d0*d0 + d1*d1) * (1.f / E_);
    float rstd = rsqrtf(var + 1e-5f);
    float* o = out + (long long)blockIdx.x * E_;
    o[threadIdx.x]       = d0 * rstd * g[threadIdx.x]       + bb[threadIdx.x];
    o[threadIdx.x + 256] = d1 * rstd * g[threadIdx.x + 256] + bb[threadIdx.x + 256];
}

__global__ void layernorm_h_k(const float* __restrict__ x, const float* __restrict__ g,
                              const float* __restrict__ bb, __half* __restrict__ out) {
    const float* xr = x + (long long)blockIdx.x * E_;
    float v0 = xr[threadIdx.x], v1 = xr[threadIdx.x + 256];
    float mean = blockReduceSum(v0 + v1) * (1.f / E_);
    float d0 = v0 - mean, d1 = v1 - mean;
    float var = blockReduceSum(d0*d0 + d1*d1) * (1.f / E_);
    float rstd = rsqrtf(var + 1e-5f);
    __half* o = out + (long long)blockIdx.x * E_;
    o[threadIdx.x]       = __float2half_rn(d0 * rstd * g[threadIdx.x]       + bb[threadIdx.x]);
    o[threadIdx.x + 256] = __float2half_rn(d1 * rstd * g[threadIdx.x + 256] + bb[threadIdx.x + 256]);
}

// ---------------- causal softmax, in-place ----------------
__global__ void softmax_causal_k(float* __restrict__ attn) {
    long long z = blockIdx.y;
    int t = blockIdx.x;
    float* row = attn + z * (long long)(T_*T_) + (long long)t * T_;
    int len = t + 1;
    float mx = -1e30f;
    for (int s = threadIdx.x; s < len; s += 256) mx = fmaxf(mx, row[s]);
    mx = blockReduceMax(mx);
    float sum = 0.f;
    for (int s = threadIdx.x; s < len; s += 256) sum += expf(row[s] - mx);
    sum = blockReduceSum(sum);
    float inv = 1.f / sum;
    for (int s = threadIdx.x; s < len; s += 256) row[s] = expf(row[s] - mx) * inv;
    for (int s = len + threadIdx.x; s < T_; s += 256) row[s] = 0.f;
}

// ============================================================================
// FP16 tensor-core GEMM (HMMA m16n8k16, fp32 accumulate).
// C[M,N] = alpha * A[M,K] @ B^T  with B stored [N][K] row-major half.
// 128x128 tile, BK=16, 256 threads (8 warps, each 64x32), cp.async 4 stages.
// Smem per stage: A 128x24h + B 128x24h = 12288 B; 4 stages = 48 KB.
// ============================================================================
#define HW 24                       // halves per smem row (16 data + 8 pad)
#define HTILE (128*HW)              // 3072 halves per tile
#define HSTAGE_BYTES (2*HTILE*2)    // 12288
#define SMEM_H_BYTES (4*HSTAGE_BYTES)

template<bool HASBIAS, bool HASRES, typename TC>
__device__ __forceinline__
void gemm_h_body(const __half* __restrict__ A, const __half* __restrict__ Bm,
                 TC* __restrict__ C,
                 int K, int lda, int ldb, int ldc,
                 const float* __restrict__ bias,
                 const float* __restrict__ resid,
                 float alpha, int row0, int col0) {
    extern __shared__ __align__(16) char dsm[];

    const int tid  = threadIdx.x;
    const int lane = tid & 31;
    const int wid  = tid >> 5;
    const int warpM = wid >> 2;          // 0..1
    const int warpN = wid & 3;           // 0..3
    const int g    = lane >> 2;
    const int tg   = lane & 3;

    const int r  = tid >> 1;             // 0..127 row in tile
    const int c8 = (tid & 1) * 8;        // 0 or 8  (k offset, halves)

    const __half* Ag = A  + (long long)(row0 + r) * lda + c8;
    const __half* Bg = Bm + (long long)(col0 + r) * ldb + c8;

    const uint32_t sbase = (uint32_t)__cvta_generic_to_shared(dsm);
    const uint32_t sA = sbase + (r * HW + c8) * 2;
    const uint32_t sB = sbase + HTILE * 2 + (r * HW + c8) * 2;

    const int KT = K >> 4;

    auto issue = [&](int kt, int slot) {
        const uint32_t off = slot * HSTAGE_BYTES;
        CP16(sA + off, Ag + (long long)kt * 16);
        CP16(sB + off, Bg + (long long)kt * 16);
    };

    float acc[4][4][4];
    #pragma unroll
    for (int i = 0; i < 4; i++)
        #pragma unroll
        for (int j = 0; j < 4; j++)
            #pragma unroll
            for (int rr = 0; rr < 4; rr++) acc[i][j][rr] = 0.f;

    #pragma unroll
    for (int i = 0; i < 3; i++) {
        if (i < KT) issue(i, i);
        CP_COMMIT();
    }

    for (int kt = 0; kt < KT; kt++) {
        CP_WAIT2();
        __syncthreads();

        const int nx = kt + 3;
        if (nx < KT) issue(nx, nx & 3);
        CP_COMMIT();

        const __half* As = (const __half*)(dsm + (kt & 3) * HSTAGE_BYTES);
        const __half* Bs = As + HTILE;

        uint32_t af[4][4];
        #pragma unroll
        for (int im = 0; im < 4; im++) {
            const int rr = warpM * 64 + im * 16 + g;
            af[im][0] = *(const uint32_t*)(As + rr * HW + 2 * tg);
            af[im][1] = *(const uint32_t*)(As + (rr + 8) * HW + 2 * tg);
            af[im][2] = *(const uint32_t*)(As + rr * HW + 8 + 2 * tg);
            af[im][3] = *(const uint32_t*)(As + (rr + 8) * HW + 8 + 2 * tg);
        }
        uint32_t bf[4][2];
        #pragma unroll
        for (int in = 0; in < 4; in++) {
            const int c = warpN * 32 + in * 8 + g;
            bf[in][0] = *(const uint32_t*)(Bs + c * HW + 2 * tg);
            bf[in][1] = *(const uint32_t*)(Bs + c * HW + 8 + 2 * tg);
        }
        #pragma unroll
        for (int im = 0; im < 4; im++)
            #pragma unroll
            for (int in = 0; in < 4; in++)
                mma_f16(acc[im][in], af[im], bf[in]);

        __syncthreads();
    }

    // ---- epilogue ----
    #pragma unroll
    for (int im = 0; im < 4; im++) {
        #pragma unroll
        for (int half = 0; half < 2; half++) {
            const int gm = row0 + warpM * 64 + im * 16 + g + half * 8;
            TC* crow = C + (long long)gm * ldc;
            const float* rrow = HASRES ? (resid + (long long)gm * ldc) : nullptr;
            #pragma unroll
            for (int in = 0; in < 4; in++) {
                const int gn = col0 + warpN * 32 + in * 8 + tg * 2;
                float vx = acc[im][in][half * 2 + 0] * alpha;
                float vy = acc[im][in][half * 2 + 1] * alpha;
                if (HASBIAS) { vx += bias[gn]; vy += bias[gn + 1]; }
                if (HASRES) {
                    float2 rr = *(const float2*)(rrow + gn);
                    vx += rr.x; vy += rr.y;
                }
                st_from_float(crow + gn, vx);
                st_from_float(crow + gn + 1, vy);
            }
        }
    }
}

// batched entry
template<bool HASBIAS, bool HASRES, bool CAUSAL, typename TC>
__global__ __launch_bounds__(256, 2)
void gemm_h_k(const __half* __restrict__ A, const __half* __restrict__ Bm,
              TC* __restrict__ C,
              int K, int lda, int ldb, int ldc,
              int innerCnt,
              long long soA, long long siA,
              long long soB, long long siB,
              long long soC, long long siC,
              const float* __restrict__ bias,
              const float* __restrict__ resid,
              float alpha) {
    const int row0 = blockIdx.y * 128;
    const int col0 = blockIdx.x * 128;
    if (CAUSAL && col0 > row0 + 127) return;
    int bz = blockIdx.z;
    int zo = bz / innerCnt;
    int zi = bz - zo * innerCnt;
    A  += zo * soA + zi * siA;
    Bm += zo * soB + zi * siB;
    C  += zo * soC + zi * siC;
    if (HASRES) resid += zo * soC + zi * siC;
    gemm_h_body<HASBIAS, HASRES, TC>(A, Bm, C, K, lda, ldb, ldc,
                                     bias, resid, alpha, row0, col0);
}

// fused QKV (half outputs)
__global__ __launch_bounds__(256, 2)
void gemm_h_qkv_k(const __half* __restrict__ A,
                  const __half* __restrict__ W0, const __half* __restrict__ W1,
                  const __half* __restrict__ W2,
                  __half* __restrict__ C0, __half* __restrict__ C1,
                  __half* __restrict__ C2) {
    const int row0 = blockIdx.y * 128;
    const int col0 = blockIdx.x * 128;
    const __half* Bm = (blockIdx.z == 0) ? W0 : (blockIdx.z == 1) ? W1 : W2;
    __half* C = (blockIdx.z == 0) ? C0 : (blockIdx.z == 1) ? C1 : C2;
    gemm_h_body<false, false, __half>(A, Bm, C, E_, E_, E_, E_,
                                      nullptr, nullptr, 1.f, row0, col0);
}

// ---------------- generic batched SGEMM (small/odd shapes, typed B/C) ----------------
#define BM 64
#define BN 64
#define BKK 16

template<bool RELU, bool HASBIAS, bool HASRES, bool CAUSALK, typename TB, typename TC>
__global__ __launch_bounds__(256)
void gemm_k(const float* __restrict__ A, const TB* __restrict__ Bm,
            TC* __restrict__ C,
            int M, int N, int K, int lda, int ldb, int ldc,
            int innerCnt,
            long long soA, long long siA,
            long long soB, long long siB,
            long long soC, long long siC,
            const float* __restrict__ bias,
            const float* __restrict__ resid,
            float alpha) {
    int row0 = blockIdx.y * BM;
    int col0 = blockIdx.x * BN;
    int bz = blockIdx.z;
    int zo = bz / innerCnt;
    int zi = bz - zo * innerCnt;
    A  += zo * soA + zi * siA;
    Bm += zo * soB + zi * siB;
    C  += zo * soC + zi * siC;
    const float* R = resid;
    if (HASRES) R += zo * soC + zi * siC;

    __shared__ float As[BKK][BM];
    __shared__ float Bs[BKK][BN + 4];

    int tid = threadIdx.x;
    int tx = tid & 15;
    int ty = tid >> 4;
    float acc[4][4] = {};

    int Kend = K;
    if (CAUSALK) { int ke = row0 + BM; Kend = ke < K ? ke : K; }

    for (int k0 = 0; k0 < Kend; k0 += BKK) {
        #pragma unroll
        for (int i = 0; i < 4; i++) {
            int li = tid * 4 + i;
            int m = li >> 4, k = li & 15;
            int gm = row0 + m, gk = k0 + k;
            float v = 0.f;
            if (gm < M && gk < K) v = A[(long long)gm * lda + gk];
            As[k][m] = v;
        }
        #pragma unroll
        for (int i = 0; i < 4; i++) {
            int li = tid * 4 + i;
            int k = li >> 6, n = li & 63;
            int gk = k0 + k, gn = col0 + n;
            float v = 0.f;
            if (gk < K && gn < N) v = ld_as_float(Bm + (long long)gk * ldb + gn);
            Bs[k][n] = v;
        }
        __syncthreads();
        #pragma unroll
        for (int k = 0; k < BKK; k++) {
            float4 a4 = *(const float4*)&As[k][ty * 4];
            float4 b4 = *(const float4*)&Bs[k][tx * 4];
            float a[4] = {a4.x, a4.y, a4.z, a4.w};
            float b[4] = {b4.x, b4.y, b4.z, b4.w};
            #pragma unroll
            for (int i = 0; i < 4; i++)
                #pragma unroll
                for (int j = 0; j < 4; j++)
                    acc[i][j] = fmaf(a[i], b[j], acc[i][j]);
        }
        __syncthreads();
    }

    #pragma unroll
    for (int i = 0; i < 4; i++) {
        int gm = row0 + ty * 4 + i;
        if (gm >= M) continue;
        #pragma unroll
        for (int j = 0; j < 4; j++) {
            int gn = col0 + tx * 4 + j;
            if (gn >= N) continue;
            float v = acc[i][j] * alpha;
            if (HASBIAS) v += bias[gn];
            if (HASRES)  v += R[(long long)gm * ldc + gn];
            if (RELU)    v = fmaxf(v, 0.f);
            st_from_float(C + (long long)gm * ldc + gn, v);
        }
    }
}

// ---------------- host launcher ----------------
extern "C" void kernel_launch(void* const* d_in, const int* in_sizes, int n_in,
                              void* d_out, int out_size) {
    const int*   idx   = (const int*)  d_in[0];
    const float* tok   = (const float*)d_in[1];
    const float* pos   = (const float*)d_in[2];
    const float* ln1_g = (const float*)d_in[3];
    const float* ln1_b = (const float*)d_in[4];
    const float* Wq    = (const float*)d_in[5];
    const float* Wk    = (const float*)d_in[6];
    const float* Wv    = (const float*)d_in[7];
    const float* Wo    = (const float*)d_in[8];
    const float* bo    = (const float*)d_in[9];
    const float* ln2_g = (const float*)d_in[10];
    const float* ln2_b = (const float*)d_in[11];
    const float* W1    = (const float*)d_in[12];
    const float* b1    = (const float*)d_in[13];
    const float* W2    = (const float*)d_in[14];
    const float* b2    = (const float*)d_in[15];
    const float* lnf_g = (const float*)d_in[16];
    const float* lnf_b = (const float*)d_in[17];
    const float* Wlm   = (const float*)d_in[18];

    float* out    = (float*)d_out;
    float* logits = out;                                  // (B,T,V)
    float* attn   = out + (long long)B_*T_*V_;            // (L,B,H,T,T)
    const long long ATTN1 = (long long)B_*H_*T_*T_;

    float *x, *h, *m;
    __half *hh, *qh, *kh, *vh, *yh, *wh, *wlmh;
    cudaGetSymbolAddress((void**)&x, g_x);
    cudaGetSymbolAddress((void**)&h, g_h);
    cudaGetSymbolAddress((void**)&m, g_m);
    cudaGetSymbolAddress((void**)&hh, g_hh);
    cudaGetSymbolAddress((void**)&qh, g_qh);
    cudaGetSymbolAddress((void**)&kh, g_kh);
    cudaGetSymbolAddress((void**)&vh, g_vh);
    cudaGetSymbolAddress((void**)&yh, g_yh);
    cudaGetSymbolAddress((void**)&wh, g_wh);
    cudaGetSymbolAddress((void**)&wlmh, g_wlmh);

    cudaFuncSetAttribute(gemm_h_qkv_k,
        cudaFuncAttributeMaxDynamicSharedMemorySize, SMEM_H_BYTES);
    cudaFuncSetAttribute(gemm_h_k<false,false,true,float>,
        cudaFuncAttributeMaxDynamicSharedMemorySize, SMEM_H_BYTES);
    cudaFuncSetAttribute(gemm_h_k<true,true,false,float>,
        cudaFuncAttributeMaxDynamicSharedMemorySize, SMEM_H_BYTES);
    cudaFuncSetAttribute(gemm_h_k<false,false,false,float>,
        cudaFuncAttributeMaxDynamicSharedMemorySize, SMEM_H_BYTES);

    const long long WSZ = (long long)E_*E_;
    __half* wqT = wh;                     // [E][E] transposed per layer
    __half* wkT = wh + L_*WSZ;
    __half* wvT = wh + 2*L_*WSZ;
    __half* woT = wh + 3*L_*WSZ;

    // pre-pass: transpose + convert weights to half [N][K]
    {
        dim3 gT(E_/32, E_/32);            // (16,16)
        for (int l = 0; l < L_; l++) {
            transpose_half_k<<<gT, 256>>>(Wq + l*WSZ, wqT + l*WSZ, E_, E_);
            transpose_half_k<<<gT, 256>>>(Wk + l*WSZ, wkT + l*WSZ, E_, E_);
            transpose_half_k<<<gT, 256>>>(Wv + l*WSZ, wvT + l*WSZ, E_, E_);
            transpose_half_k<<<gT, 256>>>(Wo + l*WSZ, woT + l*WSZ, E_, E_);
        }
        dim3 gLMt(V_/32, E_/32);          // (1000,16)
        transpose_half_k<<<gLMt, 256>>>(Wlm, wlmh, E_, V_);
    }

    // embedding
    {
        int n = BT_*E_;
        embed_k<<<(n + 255) / 256, 256>>>(idx, tok, pos, x);
    }

    dim3 gE(E_ / 128, BT_ / 128);               // (4, 32)    proj
    dim3 gQKV(E_ / 128, BT_ / 128, 3);          // (4, 32, 3) fused QKV
    dim3 gLM(V_ / 128, BT_ / 128);              // (250, 32)  lm head
    dim3 gS(T_ / 128, T_ / 128, B_*H_);         // (8, 8, 32) scores
    dim3 gAV(1, T_ / 64, B_*H_);                // (1, 16,32) attn @ V
    dim3 gM1((HID_ + 63) / 64, BT_ / 64);       // (2, 64)    mlp1
    const float scale = 0.125f;                 // 1/sqrt(64)

    for (int l = 0; l < L_; l++) {
        float* attnL = attn + (long long)l * ATTN1;

        layernorm_h_k<<<BT_, 256>>>(x, ln1_g + l*E_, ln1_b + l*E_, hh);

        // q/k/v = h @ W  (half in/out, fused)
        gemm_h_qkv_k<<<gQKV, 256, SMEM_H_BYTES>>>(
            hh, wqT + l*WSZ, wkT + l*WSZ, wvT + l*WSZ, qh, kh, vh);

        // scores = scale * Q @ K^T  (both [T][E] half slices; causal skip)
        gemm_h_k<false,false,true,float><<<gS, 256, SMEM_H_BYTES>>>(
            qh, kh, attnL, HD_, E_, E_, T_,
            H_,
            (long long)T_*E_, (long long)HD_,
            (long long)T_*E_, (long long)HD_,
            (long long)H_*T_*T_, (long long)T_*T_,
            nullptr, nullptr, scale);

        softmax_causal_k<<<dim3(T_, B_*H_), 256>>>(attnL);

        // y = P @ V  (fp32 SIMT, causal-K bound; half V in, half y out)
        gemm_k<false,false,false,true,__half,__half><<<gAV, 256>>>(
            attnL, vh, yh, T_, HD_, T_, T_, E_, E_,
            H_,
            (long long)H_*T_*T_, (long long)T_*T_,
            (long long)T_*E_, (long long)HD_,
            (long long)T_*E_, (long long)HD_,
            nullptr, nullptr, 1.f);

        // x = x + y @ Wo + bo
        gemm_h_k<true,true,false,float><<<gE, 256, SMEM_H_BYTES>>>(
            yh, woT + l*WSZ, x, E_, E_, E_, E_,
            1, 0,0, 0,0, 0,0, bo + l*E_, x, 1.f);

        layernorm_f_k<<<BT_, 256>>>(x, ln2_g + l*E_, ln2_b + l*E_, h);

        // m = relu(h @ W1 + b1)   (fp32 path)
        gemm_k<true,true,false,false,float,float><<<gM1, 256>>>(
            h, W1 + (long long)l*E_*HID_, m, BT_, HID_, E_, E_, HID_, HID_,
            1, 0,0, 0,0, 0,0, b1 + l*HID_, nullptr, 1.f);

        // x = x + m @ W2 + b2
        gemm_k<false,true,true,false,float,float><<<dim3(E_/64, BT_/64), 256>>>(
            m, W2 + (long long)l*HID_*E_, x, BT_, E_, HID_, HID_, E_, E_,
            1, 0,0, 0,0, 0,0, b2 + l*E_, x, 1.f);
    }

    // final LN + LM head
    layernorm_h_k<<<BT_, 256>>>(x, lnf_g, lnf_b, hh);
    gemm_h_k<false,false,false,float><<<gLM, 256, SMEM_H_BYTES>>>(
        hh, wlmh, logits, E_, E_, E_, V_,
        1, 0,0, 0,0, 0,0, nullptr, nullptr, 1.f);
}

// round 13
// speedup vs baseline: 1.5437x; 1.3022x over previous
#include <cuda_runtime.h>
#include <cuda_fp16.h>
#include <cstdint>

// Problem constants
#define B_   4
#define T_   1024
#define E_   512
#define H_   8
#define L_   4
#define V_   32000
#define HID_ 100
#define HD_  64
#define BT_  (B_*T_)

// ---------------- scratch (no allocations allowed) ----------------
__device__ float  g_x[BT_*E_];
__device__ float  g_h[BT_*E_];          // ln2 output (fp32, MLP path)
__device__ __half g_hh[BT_*E_];         // ln1/lnf output (half, GEMM path)
__device__ __half g_qh[BT_*E_];
__device__ __half g_kh[BT_*E_];
__device__ __half g_vh[BT_*E_];
__device__ __half g_vth[BT_*E_];        // V^T per (b,h): [32][64][T]
__device__ __half g_yh[BT_*E_];
__device__ float  g_m[BT_*HID_];
__device__ __half g_ph[(size_t)B_*H_*T_*T_];   // fp16 probs (64MB)
__device__ __half g_wh[4*L_*E_*E_];     // transposed half Wq|Wk|Wv|Wo  ([N][K])
__device__ __half g_wlmh[(size_t)V_*E_]; // transposed half Wlm ([V][E])

// ---------------- helpers ----------------
__device__ __forceinline__ float ld_as_float(const float* p)  { return *p; }
__device__ __forceinline__ float ld_as_float(const __half* p) { return __half2float(*p); }
__device__ __forceinline__ void st_from_float(float* p, float v)  { *p = v; }
__device__ __forceinline__ void st_from_float(__half* p, float v) { *p = __float2half_rn(v); }

__device__ __forceinline__ void mma_f16(float* c, const uint32_t* a, const uint32_t* b) {
    asm volatile(
      "mma.sync.aligned.m16n8k16.row.col.f32.f16.f16.f32 "
      "{%0,%1,%2,%3}, {%4,%5,%6,%7}, {%8,%9}, {%0,%1,%2,%3};\n"
      : "+f"(c[0]), "+f"(c[1]), "+f"(c[2]), "+f"(c[3])
      : "r"(a[0]), "r"(a[1]), "r"(a[2]), "r"(a[3]), "r"(b[0]), "r"(b[1]));
}

#define CP16(su32, gptr) \
    asm volatile("cp.async.ca.shared.global [%0], [%1], 16;" :: "r"(su32), "l"(gptr) : "memory")
#define CP_COMMIT() asm volatile("cp.async.commit_group;" ::: "memory")
#define CP_WAIT2()  asm volatile("cp.async.wait_group 2;"  ::: "memory")

// ---------------- block reductions ----------------
__device__ __forceinline__ float blockReduceSum(float v) {
    __shared__ float sh[32];
    int lane = threadIdx.x & 31, w = threadIdx.x >> 5;
    #pragma unroll
    for (int o = 16; o > 0; o >>= 1) v += __shfl_xor_sync(0xffffffffu, v, o);
    if (lane == 0) sh[w] = v;
    __syncthreads();
    v = (threadIdx.x < (blockDim.x >> 5)) ? sh[threadIdx.x] : 0.f;
    if (w == 0) {
        #pragma unroll
        for (int o = 16; o > 0; o >>= 1) v += __shfl_xor_sync(0xffffffffu, v, o);
        if (lane == 0) sh[0] = v;
    }
    __syncthreads();
    float r = sh[0];
    __syncthreads();
    return r;
}

__device__ __forceinline__ float blockReduceMax(float v) {
    __shared__ float sh[32];
    int lane = threadIdx.x & 31, w = threadIdx.x >> 5;
    #pragma unroll
    for (int o = 16; o > 0; o >>= 1) v = fmaxf(v, __shfl_xor_sync(0xffffffffu, v, o));
    if (lane == 0) sh[w] = v;
    __syncthreads();
    v = (threadIdx.x < (blockDim.x >> 5)) ? sh[threadIdx.x] : -1e30f;
    if (w == 0) {
        #pragma unroll
        for (int o = 16; o > 0; o >>= 1) v = fmaxf(v, __shfl_xor_sync(0xffffffffu, v, o));
        if (lane == 0) sh[0] = v;
    }
    __syncthreads();
    float r = sh[0];
    __syncthreads();
    return r;
}

// ---------------- transpose + convert to half: src[R][C] f32 -> dst[C][R] half ----------------
__global__ void transpose_half_k(const float* __restrict__ src, __half* __restrict__ dst,
                                 int R, int Cc) {
    __shared__ float tile[32][33];
    int c0 = blockIdx.x * 32, r0 = blockIdx.y * 32;
    int tx = threadIdx.x & 31, ty = threadIdx.x >> 5;   // 256 threads
    #pragma unroll
    for (int i = ty; i < 32; i += 8)
        tile[i][tx] = src[(long long)(r0 + i) * Cc + c0 + tx];
    __syncthreads();
    #pragma unroll
    for (int i = ty; i < 32; i += 8)
        dst[(long long)(c0 + i) * R + r0 + tx] = __float2half_rn(tile[tx][i]);
}

// ---------------- V transpose: vh [B*T][E] half -> vt [(b*H+h)][HD][T] half ----------------
__global__ void transpose_v_k(const __half* __restrict__ vh, __half* __restrict__ vt) {
    __shared__ __half tile[32][33];
    int b  = blockIdx.z;
    int k0 = blockIdx.x * 32, e0 = blockIdx.y * 32;
    int tx = threadIdx.x & 31, ty = threadIdx.x >> 5;
    #pragma unroll
    for (int i = ty; i < 32; i += 8)
        tile[i][tx] = vh[(long long)(b * T_ + k0 + i) * E_ + e0 + tx];
    __syncthreads();
    #pragma unroll
    for (int i = ty; i < 32; i += 8) {
        int e = e0 + i;
        int h = e >> 6, n = e & 63;
        vt[((long long)(b * H_ + h) * HD_ + n) * T_ + k0 + tx] = tile[tx][i];
    }
}

// ---------------- embedding ----------------
__global__ void embed_k(const int* __restrict__ idx, const float* __restrict__ tok,
                        const float* __restrict__ pos, float* __restrict__ x) {
    int i = blockIdx.x * 256 + threadIdx.x;
    if (i >= BT_*E_) return;
    int e  = i & (E_-1);
    int bt = i >> 9;
    int t  = bt & (T_-1);
    x[i] = tok[(long long)idx[bt]*E_ + e] + pos[t*E_ + e];
}

// ---------------- layernorm: fp32 out / half out ----------------
__global__ void layernorm_f_k(const float* __restrict__ x, const float* __restrict__ g,
                              const float* __restrict__ bb, float* __restrict__ out) {
    const float* xr = x + (long long)blockIdx.x * E_;
    float v0 = xr[threadIdx.x], v1 = xr[threadIdx.x + 256];
    float mean = blockReduceSum(v0 + v1) * (1.f / E_);
    float d0 = v0 - mean, d1 = v1 - mean;
    float var = blockReduceSum(d0*d0 + d1*d1) * (1.f / E_);
    float rstd = rsqrtf(var + 1e-5f);
    float* o = out + (long long)blockIdx.x * E_;
    o[threadIdx.x]       = d0 * rstd * g[threadIdx.x]       + bb[threadIdx.x];
    o[threadIdx.x + 256] = d1 * rstd * g[threadIdx.x + 256] + bb[threadIdx.x + 256];
}

__global__ void layernorm_h_k(const float* __restrict__ x, const float* __restrict__ g,
                              const float* __restrict__ bb, __half* __restrict__ out) {
    const float* xr = x + (long long)blockIdx.x * E_;
    float v0 = xr[threadIdx.x], v1 = xr[threadIdx.x + 256];
    float mean = blockReduceSum(v0 + v1) * (1.f / E_);
    float d0 = v0 - mean, d1 = v1 - mean;
    float var = blockReduceSum(d0*d0 + d1*d1) * (1.f / E_);
    float rstd = rsqrtf(var + 1e-5f);
    __half* o = out + (long long)blockIdx.x * E_;
    o[threadIdx.x]       = __float2half_rn(d0 * rstd * g[threadIdx.x]       + bb[threadIdx.x]);
    o[threadIdx.x + 256] = __float2half_rn(d1 * rstd * g[threadIdx.x + 256] + bb[threadIdx.x + 256]);
}

// ---------------- fused causal softmax: single read, dual write (f32 + f16) ----------------
__global__ void softmax_fused_k(float* __restrict__ attn, __half* __restrict__ ph) {
    const int tid = threadIdx.x;
    const long long z = blockIdx.y;
    const int t = blockIdx.x;
    float*  row  = attn + z * (long long)(T_*T_) + (long long)t * T_;
    __half* hrow = ph   + z * (long long)(T_*T_) + (long long)t * T_;
    const int len = t + 1;
    const int s0 = tid * 4;

    float4 v = *(const float4*)(row + s0);
    float vv[4] = {v.x, v.y, v.z, v.w};

    float mx = -1e30f;
    #pragma unroll
    for (int i = 0; i < 4; i++) if (s0 + i < len) mx = fmaxf(mx, vv[i]);
    mx = blockReduceMax(mx);

    float e[4];
    float sum = 0.f;
    #pragma unroll
    for (int i = 0; i < 4; i++) {
        e[i] = (s0 + i < len) ? expf(vv[i] - mx) : 0.f;
        sum += e[i];
    }
    sum = blockReduceSum(sum);
    const float inv = 1.f / sum;

    float4 o;
    o.x = e[0] * inv; o.y = e[1] * inv; o.z = e[2] * inv; o.w = e[3] * inv;
    *(float4*)(row + s0) = o;
    *(__half2*)(hrow + s0)     = __floats2half2_rn(o.x, o.y);
    *(__half2*)(hrow + s0 + 2) = __floats2half2_rn(o.z, o.w);
}

// ============================================================================
// FP16 tensor-core GEMM (HMMA m16n8k16, fp32 accumulate), 128x128 tile.
// ============================================================================
#define HW 24                       // halves per smem row (16 data + 8 pad)
#define HTILE (128*HW)
#define HSTAGE_BYTES (2*HTILE*2)    // 12288
#define SMEM_H_BYTES (4*HSTAGE_BYTES)

template<bool HASBIAS, bool HASRES, typename TC>
__device__ __forceinline__
void gemm_h_body(const __half* __restrict__ A, const __half* __restrict__ Bm,
                 TC* __restrict__ C,
                 int K, int lda, int ldb, int ldc,
                 const float* __restrict__ bias,
                 const float* __restrict__ resid,
                 float alpha, int row0, int col0) {
    extern __shared__ __align__(16) char dsm[];

    const int tid  = threadIdx.x;
    const int lane = tid & 31;
    const int wid  = tid >> 5;
    const int warpM = wid >> 2;
    const int warpN = wid & 3;
    const int g    = lane >> 2;
    const int tg   = lane & 3;

    const int r  = tid >> 1;
    const int c8 = (tid & 1) * 8;

    const __half* Ag = A  + (long long)(row0 + r) * lda + c8;
    const __half* Bg = Bm + (long long)(col0 + r) * ldb + c8;

    const uint32_t sbase = (uint32_t)__cvta_generic_to_shared(dsm);
    const uint32_t sA = sbase + (r * HW + c8) * 2;
    const uint32_t sB = sbase + HTILE * 2 + (r * HW + c8) * 2;

    const int KT = K >> 4;

    auto issue = [&](int kt, int slot) {
        const uint32_t off = slot * HSTAGE_BYTES;
        CP16(sA + off, Ag + (long long)kt * 16);
        CP16(sB + off, Bg + (long long)kt * 16);
    };

    float acc[4][4][4];
    #pragma unroll
    for (int i = 0; i < 4; i++)
        #pragma unroll
        for (int j = 0; j < 4; j++)
            #pragma unroll
            for (int rr = 0; rr < 4; rr++) acc[i][j][rr] = 0.f;

    #pragma unroll
    for (int i = 0; i < 3; i++) {
        if (i < KT) issue(i, i);
        CP_COMMIT();
    }

    for (int kt = 0; kt < KT; kt++) {
        CP_WAIT2();
        __syncthreads();

        const int nx = kt + 3;
        if (nx < KT) issue(nx, nx & 3);
        CP_COMMIT();

        const __half* As = (const __half*)(dsm + (kt & 3) * HSTAGE_BYTES);
        const __half* Bs = As + HTILE;

        uint32_t af[4][4];
        #pragma unroll
        for (int im = 0; im < 4; im++) {
            const int rr = warpM * 64 + im * 16 + g;
            af[im][0] = *(const uint32_t*)(As + rr * HW + 2 * tg);
            af[im][1] = *(const uint32_t*)(As + (rr + 8) * HW + 2 * tg);
            af[im][2] = *(const uint32_t*)(As + rr * HW + 8 + 2 * tg);
            af[im][3] = *(const uint32_t*)(As + (rr + 8) * HW + 8 + 2 * tg);
        }
        uint32_t bf[4][2];
        #pragma unroll
        for (int in = 0; in < 4; in++) {
            const int c = warpN * 32 + in * 8 + g;
            bf[in][0] = *(const uint32_t*)(Bs + c * HW + 2 * tg);
            bf[in][1] = *(const uint32_t*)(Bs + c * HW + 8 + 2 * tg);
        }
        #pragma unroll
        for (int im = 0; im < 4; im++)
            #pragma unroll
            for (int in = 0; in < 4; in++)
                mma_f16(acc[im][in], af[im], bf[in]);

        __syncthreads();
    }

    #pragma unroll
    for (int im = 0; im < 4; im++) {
        #pragma unroll
        for (int half = 0; half < 2; half++) {
            const int gm = row0 + warpM * 64 + im * 16 + g + half * 8;
            TC* crow = C + (long long)gm * ldc;
            const float* rrow = HASRES ? (resid + (long long)gm * ldc) : nullptr;
            #pragma unroll
            for (int in = 0; in < 4; in++) {
                const int gn = col0 + warpN * 32 + in * 8 + tg * 2;
                float vx = acc[im][in][half * 2 + 0] * alpha;
                float vy = acc[im][in][half * 2 + 1] * alpha;
                if (HASBIAS) { vx += bias[gn]; vy += bias[gn + 1]; }
                if (HASRES) {
                    float2 rr = *(const float2*)(rrow + gn);
                    vx += rr.x; vy += rr.y;
                }
                st_from_float(crow + gn, vx);
                st_from_float(crow + gn + 1, vy);
            }
        }
    }
}

template<bool HASBIAS, bool HASRES, bool CAUSAL, typename TC>
__global__ __launch_bounds__(256, 2)
void gemm_h_k(const __half* __restrict__ A, const __half* __restrict__ Bm,
              TC* __restrict__ C,
              int K, int lda, int ldb, int ldc,
              int innerCnt,
              long long soA, long long siA,
              long long soB, long long siB,
              long long soC, long long siC,
              const float* __restrict__ bias,
              const float* __restrict__ resid,
              float alpha) {
    const int row0 = blockIdx.y * 128;
    const int col0 = blockIdx.x * 128;
    if (CAUSAL && col0 > row0 + 127) return;
    int bz = blockIdx.z;
    int zo = bz / innerCnt;
    int zi = bz - zo * innerCnt;
    A  += zo * soA + zi * siA;
    Bm += zo * soB + zi * siB;
    C  += zo * soC + zi * siC;
    if (HASRES) resid += zo * soC + zi * siC;
    gemm_h_body<HASBIAS, HASRES, TC>(A, Bm, C, K, lda, ldb, ldc,
                                     bias, resid, alpha, row0, col0);
}

__global__ __launch_bounds__(256, 2)
void gemm_h_qkv_k(const __half* __restrict__ A,
                  const __half* __restrict__ W0, const __half* __restrict__ W1,
                  const __half* __restrict__ W2,
                  __half* __restrict__ C0, __half* __restrict__ C1,
                  __half* __restrict__ C2) {
    const int row0 = blockIdx.y * 128;
    const int col0 = blockIdx.x * 128;
    const __half* Bm = (blockIdx.z == 0) ? W0 : (blockIdx.z == 1) ? W1 : W2;
    __half* C = (blockIdx.z == 0) ? C0 : (blockIdx.z == 1) ? C1 : C2;
    gemm_h_body<false, false, __half>(A, Bm, C, E_, E_, E_, E_,
                                      nullptr, nullptr, 1.f, row0, col0);
}

// ============================================================================
// PV fp16 GEMM: Y[z] = P[z] @ V[z],  tile 128x64, causal-K (Kend=row0+128).
// P: [T][T] half (zeros beyond diag).  Vt: [64][T] half ([N][K]).
// 8 warps as 4x2, each 32x32 (2 m-tiles x 4 n-tiles).
// ============================================================================
#define PVA (128*HW)                 // A tile halves
#define PVB (64*HW)                  // B tile halves
#define PVSTAGE (PVA + PVB)          // 4608 halves = 9216 B
__global__ __launch_bounds__(256, 2)
void gemm_h_pv_k(const __half* __restrict__ P, const __half* __restrict__ Vt,
                 __half* __restrict__ Y) {
    __shared__ __align__(16) __half sm[4 * PVSTAGE];

    const int tid  = threadIdx.x;
    const int lane = tid & 31;
    const int wid  = tid >> 5;
    const int warpM = wid >> 1;          // 0..3 (32 rows each)
    const int warpN = wid & 1;           // 0..1 (32 cols each)
    const int g    = lane >> 2;
    const int tg   = lane & 3;

    const int row0 = blockIdx.y * 128;
    const int z    = blockIdx.z;
    const __half* A  = P  + (long long)z * T_ * T_;
    const __half* Bm = Vt + (long long)z * HD_ * T_;
    const int b = z >> 3, h = z & 7;
    __half* C = Y + (long long)b * T_ * E_ + h * HD_;

    const int r  = tid >> 1;
    const int c8 = (tid & 1) * 8;

    const __half* Ag = A + (long long)(row0 + r) * T_ + c8;
    const __half* Bg = Bm + (long long)r * T_ + c8;     // only tid<128 valid (r<64)

    const uint32_t sbase = (uint32_t)__cvta_generic_to_shared(sm);
    const uint32_t sA = sbase + (r * HW + c8) * 2;
    const uint32_t sB = sbase + PVA * 2 + (r * HW + c8) * 2;

    const int KT = (row0 + 128) >> 4;

    auto issue = [&](int kt, int slot) {
        const uint32_t off = slot * (PVSTAGE * 2);
        CP16(sA + off, Ag + (long long)kt * 16);
        if (tid < 128) CP16(sB + off, Bg + (long long)kt * 16);
    };

    float acc[2][4][4];
    #pragma unroll
    for (int i = 0; i < 2; i++)
        #pragma unroll
        for (int j = 0; j < 4; j++)
            #pragma unroll
            for (int rr = 0; rr < 4; rr++) acc[i][j][rr] = 0.f;

    #pragma unroll
    for (int i = 0; i < 3; i++) {
        if (i < KT) issue(i, i);
        CP_COMMIT();
    }

    for (int kt = 0; kt < KT; kt++) {
        CP_WAIT2();
        __syncthreads();

        const int nx = kt + 3;
        if (nx < KT) issue(nx, nx & 3);
        CP_COMMIT();

        const __half* As = sm + (kt & 3) * PVSTAGE;
        const __half* Bs = As + PVA;

        uint32_t af[2][4];
        #pragma unroll
        for (int im = 0; im < 2; im++) {
            const int rr = warpM * 32 + im * 16 + g;
            af[im][0] = *(const uint32_t*)(As + rr * HW + 2 * tg);
            af[im][1] = *(const uint32_t*)(As + (rr + 8) * HW + 2 * tg);
            af[im][2] = *(const uint32_t*)(As + rr * HW + 8 + 2 * tg);
            af[im][3] = *(const uint32_t*)(As + (rr + 8) * HW + 8 + 2 * tg);
        }
        uint32_t bf[4][2];
        #pragma unroll
        for (int in = 0; in < 4; in++) {
            const int c = warpN * 32 + in * 8 + g;
            bf[in][0] = *(const uint32_t*)(Bs + c * HW + 2 * tg);
            bf[in][1] = *(const uint32_t*)(Bs + c * HW + 8 + 2 * tg);
        }
        #pragma unroll
        for (int im = 0; im < 2; im++)
            #pragma unroll
            for (int in = 0; in < 4; in++)
                mma_f16(acc[im][in], af[im], bf[in]);

        __syncthreads();
    }

    #pragma unroll
    for (int im = 0; im < 2; im++) {
        #pragma unroll
        for (int half = 0; half < 2; half++) {
            const int gm = row0 + warpM * 32 + im * 16 + g + half * 8;
            __half* crow = C + (long long)gm * E_;
            #pragma unroll
            for (int in = 0; in < 4; in++) {
                const int gn = warpN * 32 + in * 8 + tg * 2;
                *(__half2*)(crow + gn) = __floats2half2_rn(
                    acc[im][in][half * 2 + 0], acc[im][in][half * 2 + 1]);
            }
        }
    }
}

// ---------------- generic batched SGEMM (small/odd shapes, typed B/C) ----------------
#define BM 64
#define BN 64
#define BKK 16

template<bool RELU, bool HASBIAS, bool HASRES, typename TB, typename TC>
__global__ __launch_bounds__(256)
void gemm_k(const float* __restrict__ A, const TB* __restrict__ Bm,
            TC* __restrict__ C,
            int M, int N, int K, int lda, int ldb, int ldc,
            const float* __restrict__ bias,
            const float* __restrict__ resid,
            float alpha) {
    int row0 = blockIdx.y * BM;
    int col0 = blockIdx.x * BN;

    __shared__ float As[BKK][BM];
    __shared__ float Bs[BKK][BN + 4];

    int tid = threadIdx.x;
    int tx = tid & 15;
    int ty = tid >> 4;
    float acc[4][4] = {};

    for (int k0 = 0; k0 < K; k0 += BKK) {
        #pragma unroll
        for (int i = 0; i < 4; i++) {
            int li = tid * 4 + i;
            int m = li >> 4, k = li & 15;
            int gm = row0 + m, gk = k0 + k;
            float v = 0.f;
            if (gm < M && gk < K) v = A[(long long)gm * lda + gk];
            As[k][m] = v;
        }
        #pragma unroll
        for (int i = 0; i < 4; i++) {
            int li = tid * 4 + i;
            int k = li >> 6, n = li & 63;
            int gk = k0 + k, gn = col0 + n;
            float v = 0.f;
            if (gk < K && gn < N) v = ld_as_float(Bm + (long long)gk * ldb + gn);
            Bs[k][n] = v;
        }
        __syncthreads();
        #pragma unroll
        for (int k = 0; k < BKK; k++) {
            float4 a4 = *(const float4*)&As[k][ty * 4];
            float4 b4 = *(const float4*)&Bs[k][tx * 4];
            float a[4] = {a4.x, a4.y, a4.z, a4.w};
            float b[4] = {b4.x, b4.y, b4.z, b4.w};
            #pragma unroll
            for (int i = 0; i < 4; i++)
                #pragma unroll
                for (int j = 0; j < 4; j++)
                    acc[i][j] = fmaf(a[i], b[j], acc[i][j]);
        }
        __syncthreads();
    }

    #pragma unroll
    for (int i = 0; i < 4; i++) {
        int gm = row0 + ty * 4 + i;
        if (gm >= M) continue;
        #pragma unroll
        for (int j = 0; j < 4; j++) {
            int gn = col0 + tx * 4 + j;
            if (gn >= N) continue;
            float v = acc[i][j] * alpha;
            if (HASBIAS) v += bias[gn];
            if (HASRES)  v += resid[(long long)gm * ldc + gn];
            if (RELU)    v = fmaxf(v, 0.f);
            st_from_float(C + (long long)gm * ldc + gn, v);
        }
    }
}

// ---------------- host launcher ----------------
extern "C" void kernel_launch(void* const* d_in, const int* in_sizes, int n_in,
                              void* d_out, int out_size) {
    const int*   idx   = (const int*)  d_in[0];
    const float* tok   = (const float*)d_in[1];
    const float* pos   = (const float*)d_in[2];
    const float* ln1_g = (const float*)d_in[3];
    const float* ln1_b = (const float*)d_in[4];
    const float* Wq    = (const float*)d_in[5];
    const float* Wk    = (const float*)d_in[6];
    const float* Wv    = (const float*)d_in[7];
    const float* Wo    = (const float*)d_in[8];
    const float* bo    = (const float*)d_in[9];
    const float* ln2_g = (const float*)d_in[10];
    const float* ln2_b = (const float*)d_in[11];
    const float* W1    = (const float*)d_in[12];
    const float* b1    = (const float*)d_in[13];
    const float* W2    = (const float*)d_in[14];
    const float* b2    = (const float*)d_in[15];
    const float* lnf_g = (const float*)d_in[16];
    const float* lnf_b = (const float*)d_in[17];
    const float* Wlm   = (const float*)d_in[18];

    float* out    = (float*)d_out;
    float* logits = out;                                  // (B,T,V)
    float* attn   = out + (long long)B_*T_*V_;            // (L,B,H,T,T)
    const long long ATTN1 = (long long)B_*H_*T_*T_;

    float *x, *h, *m;
    __half *hh, *qh, *kh, *vh, *vth, *yh, *ph, *wh, *wlmh;
    cudaGetSymbolAddress((void**)&x, g_x);
    cudaGetSymbolAddress((void**)&h, g_h);
    cudaGetSymbolAddress((void**)&m, g_m);
    cudaGetSymbolAddress((void**)&hh, g_hh);
    cudaGetSymbolAddress((void**)&qh, g_qh);
    cudaGetSymbolAddress((void**)&kh, g_kh);
    cudaGetSymbolAddress((void**)&vh, g_vh);
    cudaGetSymbolAddress((void**)&vth, g_vth);
    cudaGetSymbolAddress((void**)&yh, g_yh);
    cudaGetSymbolAddress((void**)&ph, g_ph);
    cudaGetSymbolAddress((void**)&wh, g_wh);
    cudaGetSymbolAddress((void**)&wlmh, g_wlmh);

    cudaFuncSetAttribute(gemm_h_qkv_k,
        cudaFuncAttributeMaxDynamicSharedMemorySize, SMEM_H_BYTES);
    cudaFuncSetAttribute(gemm_h_k<false,false,true,float>,
        cudaFuncAttributeMaxDynamicSharedMemorySize, SMEM_H_BYTES);
    cudaFuncSetAttribute(gemm_h_k<true,true,false,float>,
        cudaFuncAttributeMaxDynamicSharedMemorySize, SMEM_H_BYTES);
    cudaFuncSetAttribute(gemm_h_k<false,false,false,float>,
        cudaFuncAttributeMaxDynamicSharedMemorySize, SMEM_H_BYTES);

    const long long WSZ = (long long)E_*E_;
    __half* wqT = wh;
    __half* wkT = wh + L_*WSZ;
    __half* wvT = wh + 2*L_*WSZ;
    __half* woT = wh + 3*L_*WSZ;

    // pre-pass: transpose + convert weights to half [N][K]
    {
        dim3 gT(E_/32, E_/32);
        for (int l = 0; l < L_; l++) {
            transpose_half_k<<<gT, 256>>>(Wq + l*WSZ, wqT + l*WSZ, E_, E_);
            transpose_half_k<<<gT, 256>>>(Wk + l*WSZ, wkT + l*WSZ, E_, E_);
            transpose_half_k<<<gT, 256>>>(Wv + l*WSZ, wvT + l*WSZ, E_, E_);
            transpose_half_k<<<gT, 256>>>(Wo + l*WSZ, woT + l*WSZ, E_, E_);
        }
        dim3 gLMt(V_/32, E_/32);
        transpose_half_k<<<gLMt, 256>>>(Wlm, wlmh, E_, V_);
    }

    // embedding
    {
        int n = BT_*E_;
        embed_k<<<(n + 255) / 256, 256>>>(idx, tok, pos, x);
    }

    dim3 gE(E_ / 128, BT_ / 128);               // (4, 32)    proj
    dim3 gQKV(E_ / 128, BT_ / 128, 3);          // (4, 32, 3) fused QKV
    dim3 gLM(V_ / 128, BT_ / 128);              // (250, 32)  lm head
    dim3 gS(T_ / 128, T_ / 128, B_*H_);         // (8, 8, 32) scores
    dim3 gPV(1, T_ / 128, B_*H_);               // (1, 8, 32) PV fp16
    dim3 gVT(T_/32, E_/32, B_);                 // V transpose
    dim3 gM1((HID_ + 63) / 64, BT_ / 64);       // (2, 64)    mlp1
    const float scale = 0.125f;                 // 1/sqrt(64)

    for (int l = 0; l < L_; l++) {
        float* attnL = attn + (long long)l * ATTN1;

        layernorm_h_k<<<BT_, 256>>>(x, ln1_g + l*E_, ln1_b + l*E_, hh);

        gemm_h_qkv_k<<<gQKV, 256, SMEM_H_BYTES>>>(
            hh, wqT + l*WSZ, wkT + l*WSZ, wvT + l*WSZ, qh, kh, vh);

        transpose_v_k<<<gVT, 256>>>(vh, vth);

        // scores = scale * Q @ K^T
        gemm_h_k<false,false,true,float><<<gS, 256, SMEM_H_BYTES>>>(
            qh, kh, attnL, HD_, E_, E_, T_,
            H_,
            (long long)T_*E_, (long long)HD_,
            (long long)T_*E_, (long long)HD_,
            (long long)H_*T_*T_, (long long)T_*T_,
            nullptr, nullptr, scale);

        // fused softmax (writes fp32 output + fp16 probs)
        softmax_fused_k<<<dim3(T_, B_*H_), 256>>>(attnL, ph);

        // y = P @ V  (fp16 tensor cores, causal-K)
        gemm_h_pv_k<<<gPV, 256>>>(ph, vth, yh);

        // x = x + y @ Wo + bo
        gemm_h_k<true,true,false,float><<<gE, 256, SMEM_H_BYTES>>>(
            yh, woT + l*WSZ, x, E_, E_, E_, E_,
            1, 0,0, 0,0, 0,0, bo + l*E_, x, 1.f);

        layernorm_f_k<<<BT_, 256>>>(x, ln2_g + l*E_, ln2_b + l*E_, h);

        // m = relu(h @ W1 + b1)   (fp32 path)
        gemm_k<true,true,false,float,float><<<gM1, 256>>>(
            h, W1 + (long long)l*E_*HID_, m, BT_, HID_, E_, E_, HID_, HID_,
            b1 + l*HID_, nullptr, 1.f);

        // x = x + m @ W2 + b2
        gemm_k<false,true,true,float,float><<<dim3(E_/64, BT_/64), 256>>>(
            m, W2 + (long long)l*HID_*E_, x, BT_, E_, HID_, HID_, E_, E_,
            b2 + l*E_, x, 1.f);
    }

    // final LN + LM head
    layernorm_h_k<<<BT_, 256>>>(x, lnf_g, lnf_b, hh);
    gemm_h_k<false,false,false,float><<<gLM, 256, SMEM_H_BYTES>>>(
        hh, wlmh, logits, E_, E_, E_, V_,
        1, 0,0, 0,0, 0,0, nullptr, nullptr, 1.f);
}

// round 14
// speedup vs baseline: 1.7419x; 1.1284x over previous
#include <cuda_runtime.h>
#include <cuda_fp16.h>
#include <cstdint>

// Problem constants
#define B_   4
#define T_   1024
#define E_   512
#define H_   8
#define L_   4
#define V_   32000
#define HID_ 100
#define HIDP 128
#define HD_  64
#define BT_  (B_*T_)

// ---------------- scratch (no allocations allowed) ----------------
__device__ float  g_x[BT_*E_];
__device__ __half g_hh[BT_*E_];         // LN output (half, GEMM path)
__device__ __half g_qh[BT_*E_];
__device__ __half g_kh[BT_*E_];
__device__ __half g_vh[BT_*E_];
__device__ __half g_vth[BT_*E_];        // V^T per (b,h): [32][64][T]
__device__ __half g_yh[BT_*E_];
__device__ __half g_mh[BT_*HIDP];       // MLP mid (half, padded)
__device__ __half g_ph[(size_t)B_*H_*T_*T_];   // fp16 probs
__device__ __half g_wh[4*L_*E_*E_];     // transposed half Wq|Wk|Wv|Wo ([N][K])
__device__ __half g_w1h[L_*HIDP*E_];    // W1^T padded [128][512]
__device__ __half g_w2h[L_*E_*HIDP];    // W2^T padded [512][128]
__device__ __half g_wlmh[(size_t)V_*E_]; // Wlm^T ([V][E])

// ---------------- helpers ----------------
__device__ __forceinline__ void st_from_float(float* p, float v)  { *p = v; }
__device__ __forceinline__ void st_from_float(__half* p, float v) { *p = __float2half_rn(v); }

__device__ __forceinline__ void mma_f16(float* c, const uint32_t* a, const uint32_t* b) {
    asm volatile(
      "mma.sync.aligned.m16n8k16.row.col.f32.f16.f16.f32 "
      "{%0,%1,%2,%3}, {%4,%5,%6,%7}, {%8,%9}, {%0,%1,%2,%3};\n"
      : "+f"(c[0]), "+f"(c[1]), "+f"(c[2]), "+f"(c[3])
      : "r"(a[0]), "r"(a[1]), "r"(a[2]), "r"(a[3]), "r"(b[0]), "r"(b[1]));
}

#define CP16(su32, gptr) \
    asm volatile("cp.async.ca.shared.global [%0], [%1], 16;" :: "r"(su32), "l"(gptr) : "memory")
#define CP_COMMIT() asm volatile("cp.async.commit_group;" ::: "memory")
#define CP_WAIT1()  asm volatile("cp.async.wait_group 1;"  ::: "memory")
#define CP_WAIT2()  asm volatile("cp.async.wait_group 2;"  ::: "memory")

// ---------------- block reductions ----------------
__device__ __forceinline__ float blockReduceSum(float v) {
    __shared__ float sh[32];
    int lane = threadIdx.x & 31, w = threadIdx.x >> 5;
    #pragma unroll
    for (int o = 16; o > 0; o >>= 1) v += __shfl_xor_sync(0xffffffffu, v, o);
    if (lane == 0) sh[w] = v;
    __syncthreads();
    v = (threadIdx.x < (blockDim.x >> 5)) ? sh[threadIdx.x] : 0.f;
    if (w == 0) {
        #pragma unroll
        for (int o = 16; o > 0; o >>= 1) v += __shfl_xor_sync(0xffffffffu, v, o);
        if (lane == 0) sh[0] = v;
    }
    __syncthreads();
    float r = sh[0];
    __syncthreads();
    return r;
}

__device__ __forceinline__ float blockReduceMax(float v) {
    __shared__ float sh[32];
    int lane = threadIdx.x & 31, w = threadIdx.x >> 5;
    #pragma unroll
    for (int o = 16; o > 0; o >>= 1) v = fmaxf(v, __shfl_xor_sync(0xffffffffu, v, o));
    if (lane == 0) sh[w] = v;
    __syncthreads();
    v = (threadIdx.x < (blockDim.x >> 5)) ? sh[threadIdx.x] : -1e30f;
    if (w == 0) {
        #pragma unroll
        for (int o = 16; o > 0; o >>= 1) v = fmaxf(v, __shfl_xor_sync(0xffffffffu, v, o));
        if (lane == 0) sh[0] = v;
    }
    __syncthreads();
    float r = sh[0];
    __syncthreads();
    return r;
}

// ---------------- batched padded transpose: src[z][Rs][Cs] f32 -> dst[z][Cd][Rd] half ----------------
// dst[c][r] = src[r][c] if (r<Rs && c<Cs) else 0.  grid: x=Rd/32, y=Cd/32, z=batch.
__global__ void transpose_pad_k(const float* __restrict__ src, __half* __restrict__ dst,
                                int Rs, int Rd, int Cs, int Cd,
                                long long sSrc, long long sDst) {
    __shared__ float tile[32][33];
    const float* s = src + blockIdx.z * sSrc;
    __half* d = dst + blockIdx.z * sDst;
    int r0 = blockIdx.x * 32, c0 = blockIdx.y * 32;
    int tx = threadIdx.x & 31, ty = threadIdx.x >> 5;
    #pragma unroll
    for (int i = ty; i < 32; i += 8) {
        int r = r0 + i, c = c0 + tx;
        tile[i][tx] = (r < Rs && c < Cs) ? s[(long long)r * Cs + c] : 0.f;
    }
    __syncthreads();
    #pragma unroll
    for (int i = ty; i < 32; i += 8)
        d[(long long)(c0 + i) * Rd + r0 + tx] = __float2half_rn(tile[tx][i]);
}

// ---------------- V transpose: vh [B*T][E] half -> vt [(b*H+h)][HD][T] half ----------------
__global__ void transpose_v_k(const __half* __restrict__ vh, __half* __restrict__ vt) {
    __shared__ __half tile[32][33];
    int b  = blockIdx.z;
    int k0 = blockIdx.x * 32, e0 = blockIdx.y * 32;
    int tx = threadIdx.x & 31, ty = threadIdx.x >> 5;
    #pragma unroll
    for (int i = ty; i < 32; i += 8)
        tile[i][tx] = vh[(long long)(b * T_ + k0 + i) * E_ + e0 + tx];
    __syncthreads();
    #pragma unroll
    for (int i = ty; i < 32; i += 8) {
        int e = e0 + i;
        int h = e >> 6, n = e & 63;
        vt[((long long)(b * H_ + h) * HD_ + n) * T_ + k0 + tx] = tile[tx][i];
    }
}

// ---------------- embedding ----------------
__global__ void embed_k(const int* __restrict__ idx, const float* __restrict__ tok,
                        const float* __restrict__ pos, float* __restrict__ x) {
    int i = blockIdx.x * 256 + threadIdx.x;
    if (i >= BT_*E_) return;
    int e  = i & (E_-1);
    int bt = i >> 9;
    int t  = bt & (T_-1);
    x[i] = tok[(long long)idx[bt]*E_ + e] + pos[t*E_ + e];
}

// ---------------- layernorm (half out) ----------------
__global__ void layernorm_h_k(const float* __restrict__ x, const float* __restrict__ g,
                              const float* __restrict__ bb, __half* __restrict__ out) {
    const float* xr = x + (long long)blockIdx.x * E_;
    float v0 = xr[threadIdx.x], v1 = xr[threadIdx.x + 256];
    float mean = blockReduceSum(v0 + v1) * (1.f / E_);
    float d0 = v0 - mean, d1 = v1 - mean;
    float var = blockReduceSum(d0*d0 + d1*d1) * (1.f / E_);
    float rstd = rsqrtf(var + 1e-5f);
    __half* o = out + (long long)blockIdx.x * E_;
    o[threadIdx.x]       = __float2half_rn(d0 * rstd * g[threadIdx.x]       + bb[threadIdx.x]);
    o[threadIdx.x + 256] = __float2half_rn(d1 * rstd * g[threadIdx.x + 256] + bb[threadIdx.x + 256]);
}

// ---------------- fused causal softmax: single read, dual write (f32 + f16) ----------------
__global__ void softmax_fused_k(float* __restrict__ attn, __half* __restrict__ ph) {
    const int tid = threadIdx.x;
    const long long z = blockIdx.y;
    const int t = blockIdx.x;
    float*  row  = attn + z * (long long)(T_*T_) + (long long)t * T_;
    __half* hrow = ph   + z * (long long)(T_*T_) + (long long)t * T_;
    const int len = t + 1;
    const int s0 = tid * 4;

    float4 v = *(const float4*)(row + s0);
    float vv[4] = {v.x, v.y, v.z, v.w};

    float mx = -1e30f;
    #pragma unroll
    for (int i = 0; i < 4; i++) if (s0 + i < len) mx = fmaxf(mx, vv[i]);
    mx = blockReduceMax(mx);

    float e[4];
    float sum = 0.f;
    #pragma unroll
    for (int i = 0; i < 4; i++) {
        e[i] = (s0 + i < len) ? expf(vv[i] - mx) : 0.f;
        sum += e[i];
    }
    sum = blockReduceSum(sum);
    const float inv = 1.f / sum;

    float4 o;
    o.x = e[0] * inv; o.y = e[1] * inv; o.z = e[2] * inv; o.w = e[3] * inv;
    *(float4*)(row + s0) = o;
    *(__half2*)(hrow + s0)     = __floats2half2_rn(o.x, o.y);
    *(__half2*)(hrow + s0 + 2) = __floats2half2_rn(o.z, o.w);
}

// ============================================================================
// FP16 tensor-core GEMM (HMMA m16n8k16, fp32 acc), 128x128 tile, BK=32,
// 3-stage cp.async pipeline. B stored [N][K] half.
// Smem: stage = 2 x (128 x 40h) = 20480 B; 3 stages = 61440 B.
// ============================================================================
#define HW2 40
#define HT2 (128*HW2)               // halves per tile
#define HSTB2 (2*HT2*2)             // 20480 bytes per stage
#define SMEM_H2 (3*HSTB2)           // 61440

template<bool RELU, bool HASBIAS, bool HASRES, typename TC>
__device__ __forceinline__
void gemm_h_body(const __half* __restrict__ A, const __half* __restrict__ Bm,
                 TC* __restrict__ C,
                 int K, int lda, int ldb, int ldc,
                 const float* __restrict__ bias, int nbias,
                 const float* __restrict__ resid,
                 float alpha, int row0, int col0) {
    extern __shared__ __align__(16) char dsm[];

    const int tid  = threadIdx.x;
    const int lane = tid & 31;
    const int wid  = tid >> 5;
    const int warpM = wid >> 2;
    const int warpN = wid & 3;
    const int g    = lane >> 2;
    const int tg   = lane & 3;

    const int r   = tid >> 1;
    const int c16 = (tid & 1) * 16;

    const __half* Ag = A  + (long long)(row0 + r) * lda + c16;
    const __half* Bg = Bm + (long long)(col0 + r) * ldb + c16;

    const uint32_t sbase = (uint32_t)__cvta_generic_to_shared(dsm);
    const uint32_t sA = sbase + (r * HW2 + c16) * 2;
    const uint32_t sB = sbase + HT2 * 2 + (r * HW2 + c16) * 2;

    const int KT = K >> 5;

    auto issue = [&](int kt, int slot) {
        const uint32_t off = slot * HSTB2;
        const __half* ga = Ag + (long long)kt * 32;
        const __half* gb = Bg + (long long)kt * 32;
        CP16(sA + off, ga);       CP16(sA + off + 16, ga + 8);
        CP16(sB + off, gb);       CP16(sB + off + 16, gb + 8);
    };

    float acc[4][4][4];
    #pragma unroll
    for (int i = 0; i < 4; i++)
        #pragma unroll
        for (int j = 0; j < 4; j++)
            #pragma unroll
            for (int rr = 0; rr < 4; rr++) acc[i][j][rr] = 0.f;

    if (0 < KT) issue(0, 0);
    CP_COMMIT();
    if (1 < KT) issue(1, 1);
    CP_COMMIT();

    for (int kt = 0; kt < KT; kt++) {
        CP_WAIT1();
        __syncthreads();

        const int nx = kt + 2;
        if (nx < KT) {
            int slot = nx; while (slot >= 3) slot -= 3;
            issue(nx, slot);
        }
        CP_COMMIT();

        int cs = kt; while (cs >= 3) cs -= 3;
        const __half* As = (const __half*)(dsm + cs * HSTB2);
        const __half* Bs = As + HT2;

        #pragma unroll
        for (int ks = 0; ks < 2; ks++) {
            const int kk = ks * 16;
            uint32_t af[4][4];
            #pragma unroll
            for (int im = 0; im < 4; im++) {
                const int rr = warpM * 64 + im * 16 + g;
                af[im][0] = *(const uint32_t*)(As + rr * HW2 + kk + 2 * tg);
                af[im][1] = *(const uint32_t*)(As + (rr + 8) * HW2 + kk + 2 * tg);
                af[im][2] = *(const uint32_t*)(As + rr * HW2 + kk + 8 + 2 * tg);
                af[im][3] = *(const uint32_t*)(As + (rr + 8) * HW2 + kk + 8 + 2 * tg);
            }
            uint32_t bf[4][2];
            #pragma unroll
            for (int in = 0; in < 4; in++) {
                const int c = warpN * 32 + in * 8 + g;
                bf[in][0] = *(const uint32_t*)(Bs + c * HW2 + kk + 2 * tg);
                bf[in][1] = *(const uint32_t*)(Bs + c * HW2 + kk + 8 + 2 * tg);
            }
            #pragma unroll
            for (int im = 0; im < 4; im++)
                #pragma unroll
                for (int in = 0; in < 4; in++)
                    mma_f16(acc[im][in], af[im], bf[in]);
        }
    }

    // ---- epilogue ----
    #pragma unroll
    for (int im = 0; im < 4; im++) {
        #pragma unroll
        for (int half = 0; half < 2; half++) {
            const int gm = row0 + warpM * 64 + im * 16 + g + half * 8;
            TC* crow = C + (long long)gm * ldc;
            const float* rrow = HASRES ? (resid + (long long)gm * ldc) : nullptr;
            #pragma unroll
            for (int in = 0; in < 4; in++) {
                const int gn = col0 + warpN * 32 + in * 8 + tg * 2;
                float vx = acc[im][in][half * 2 + 0] * alpha;
                float vy = acc[im][in][half * 2 + 1] * alpha;
                if (HASBIAS && gn < nbias) { vx += bias[gn]; vy += bias[gn + 1]; }
                if (HASRES) {
                    float2 rr = *(const float2*)(rrow + gn);
                    vx += rr.x; vy += rr.y;
                }
                if (RELU) { vx = fmaxf(vx, 0.f); vy = fmaxf(vy, 0.f); }
                st_from_float(crow + gn, vx);
                st_from_float(crow + gn + 1, vy);
            }
        }
    }
}

template<bool RELU, bool HASBIAS, bool HASRES, bool CAUSAL, typename TC>
__global__ __launch_bounds__(256, 2)
void gemm_h_k(const __half* __restrict__ A, const __half* __restrict__ Bm,
              TC* __restrict__ C,
              int K, int lda, int ldb, int ldc,
              int innerCnt,
              long long soA, long long siA,
              long long soB, long long siB,
              long long soC, long long siC,
              const float* __restrict__ bias, int nbias,
              const float* __restrict__ resid,
              float alpha) {
    const int row0 = blockIdx.y * 128;
    const int col0 = blockIdx.x * 128;
    if (CAUSAL && col0 > row0 + 127) return;
    int bz = blockIdx.z;
    int zo = bz / innerCnt;
    int zi = bz - zo * innerCnt;
    A  += zo * soA + zi * siA;
    Bm += zo * soB + zi * siB;
    C  += zo * soC + zi * siC;
    if (HASRES) resid += zo * soC + zi * siC;
    gemm_h_body<RELU, HASBIAS, HASRES, TC>(A, Bm, C, K, lda, ldb, ldc,
                                           bias, nbias, resid, alpha, row0, col0);
}

__global__ __launch_bounds__(256, 2)
void gemm_h_qkv_k(const __half* __restrict__ A,
                  const __half* __restrict__ W0, const __half* __restrict__ W1w,
                  const __half* __restrict__ W2w,
                  __half* __restrict__ C0, __half* __restrict__ C1,
                  __half* __restrict__ C2) {
    const int row0 = blockIdx.y * 128;
    const int col0 = blockIdx.x * 128;
    const __half* Bm = (blockIdx.z == 0) ? W0 : (blockIdx.z == 1) ? W1w : W2w;
    __half* C = (blockIdx.z == 0) ? C0 : (blockIdx.z == 1) ? C1 : C2;
    gemm_h_body<false, false, false, __half>(A, Bm, C, E_, E_, E_, E_,
                                             nullptr, 0, nullptr, 1.f, row0, col0);
}

// ============================================================================
// PV fp16 GEMM: Y[z] = P[z] @ V[z], tile 128x64, causal-K, BK=16, 4 stages.
// ============================================================================
#define HW 24
#define PVA (128*HW)
#define PVB (64*HW)
#define PVSTAGE (PVA + PVB)
__global__ __launch_bounds__(256, 2)
void gemm_h_pv_k(const __half* __restrict__ P, const __half* __restrict__ Vt,
                 __half* __restrict__ Y) {
    __shared__ __align__(16) __half sm[4 * PVSTAGE];

    const int tid  = threadIdx.x;
    const int lane = tid & 31;
    const int wid  = tid >> 5;
    const int warpM = wid >> 1;
    const int warpN = wid & 1;
    const int g    = lane >> 2;
    const int tg   = lane & 3;

    const int row0 = blockIdx.y * 128;
    const int z    = blockIdx.z;
    const __half* A  = P  + (long long)z * T_ * T_;
    const __half* Bm = Vt + (long long)z * HD_ * T_;
    const int b = z >> 3, h = z & 7;
    __half* C = Y + (long long)b * T_ * E_ + h * HD_;

    const int r  = tid >> 1;
    const int c8 = (tid & 1) * 8;

    const __half* Ag = A + (long long)(row0 + r) * T_ + c8;
    const __half* Bg = Bm + (long long)r * T_ + c8;

    const uint32_t sbase = (uint32_t)__cvta_generic_to_shared(sm);
    const uint32_t sA = sbase + (r * HW + c8) * 2;
    const uint32_t sB = sbase + PVA * 2 + (r * HW + c8) * 2;

    const int KT = (row0 + 128) >> 4;

    auto issue = [&](int kt, int slot) {
        const uint32_t off = slot * (PVSTAGE * 2);
        CP16(sA + off, Ag + (long long)kt * 16);
        if (tid < 128) CP16(sB + off, Bg + (long long)kt * 16);
    };

    float acc[2][4][4];
    #pragma unroll
    for (int i = 0; i < 2; i++)
        #pragma unroll
        for (int j = 0; j < 4; j++)
            #pragma unroll
            for (int rr = 0; rr < 4; rr++) acc[i][j][rr] = 0.f;

    #pragma unroll
    for (int i = 0; i < 3; i++) {
        if (i < KT) issue(i, i);
        CP_COMMIT();
    }

    for (int kt = 0; kt < KT; kt++) {
        CP_WAIT2();
        __syncthreads();

        const int nx = kt + 3;
        if (nx < KT) issue(nx, nx & 3);
        CP_COMMIT();

        const __half* As = sm + (kt & 3) * PVSTAGE;
        const __half* Bs = As + PVA;

        uint32_t af[2][4];
        #pragma unroll
        for (int im = 0; im < 2; im++) {
            const int rr = warpM * 32 + im * 16 + g;
            af[im][0] = *(const uint32_t*)(As + rr * HW + 2 * tg);
            af[im][1] = *(const uint32_t*)(As + (rr + 8) * HW + 2 * tg);
            af[im][2] = *(const uint32_t*)(As + rr * HW + 8 + 2 * tg);
            af[im][3] = *(const uint32_t*)(As + (rr + 8) * HW + 8 + 2 * tg);
        }
        uint32_t bf[4][2];
        #pragma unroll
        for (int in = 0; in < 4; in++) {
            const int c = warpN * 32 + in * 8 + g;
            bf[in][0] = *(const uint32_t*)(Bs + c * HW + 2 * tg);
            bf[in][1] = *(const uint32_t*)(Bs + c * HW + 8 + 2 * tg);
        }
        #pragma unroll
        for (int im = 0; im < 2; im++)
            #pragma unroll
            for (int in = 0; in < 4; in++)
                mma_f16(acc[im][in], af[im], bf[in]);

        __syncthreads();
    }

    #pragma unroll
    for (int im = 0; im < 2; im++) {
        #pragma unroll
        for (int half = 0; half < 2; half++) {
            const int gm = row0 + warpM * 32 + im * 16 + g + half * 8;
            __half* crow = C + (long long)gm * E_;
            #pragma unroll
            for (int in = 0; in < 4; in++) {
                const int gn = warpN * 32 + in * 8 + tg * 2;
                *(__half2*)(crow + gn) = __floats2half2_rn(
                    acc[im][in][half * 2 + 0], acc[im][in][half * 2 + 1]);
            }
        }
    }
}

// ---------------- host launcher ----------------
extern "C" void kernel_launch(void* const* d_in, const int* in_sizes, int n_in,
                              void* d_out, int out_size) {
    const int*   idx   = (const int*)  d_in[0];
    const float* tok   = (const float*)d_in[1];
    const float* pos   = (const float*)d_in[2];
    const float* ln1_g = (const float*)d_in[3];
    const float* ln1_b = (const float*)d_in[4];
    const float* Wq    = (const float*)d_in[5];
    const float* Wk    = (const float*)d_in[6];
    const float* Wv    = (const float*)d_in[7];
    const float* Wo    = (const float*)d_in[8];
    const float* bo    = (const float*)d_in[9];
    const float* ln2_g = (const float*)d_in[10];
    const float* ln2_b = (const float*)d_in[11];
    const float* W1    = (const float*)d_in[12];
    const float* b1    = (const float*)d_in[13];
    const float* W2    = (const float*)d_in[14];
    const float* b2    = (const float*)d_in[15];
    const float* lnf_g = (const float*)d_in[16];
    const float* lnf_b = (const float*)d_in[17];
    const float* Wlm   = (const float*)d_in[18];

    float* out    = (float*)d_out;
    float* logits = out;                                  // (B,T,V)
    float* attn   = out + (long long)B_*T_*V_;            // (L,B,H,T,T)
    const long long ATTN1 = (long long)B_*H_*T_*T_;

    float *x;
    __half *hh, *qh, *kh, *vh, *vth, *yh, *mh, *ph, *wh, *w1h, *w2h, *wlmh;
    cudaGetSymbolAddress((void**)&x, g_x);
    cudaGetSymbolAddress((void**)&hh, g_hh);
    cudaGetSymbolAddress((void**)&qh, g_qh);
    cudaGetSymbolAddress((void**)&kh, g_kh);
    cudaGetSymbolAddress((void**)&vh, g_vh);
    cudaGetSymbolAddress((void**)&vth, g_vth);
    cudaGetSymbolAddress((void**)&yh, g_yh);
    cudaGetSymbolAddress((void**)&mh, g_mh);
    cudaGetSymbolAddress((void**)&ph, g_ph);
    cudaGetSymbolAddress((void**)&wh, g_wh);
    cudaGetSymbolAddress((void**)&w1h, g_w1h);
    cudaGetSymbolAddress((void**)&w2h, g_w2h);
    cudaGetSymbolAddress((void**)&wlmh, g_wlmh);

    cudaFuncSetAttribute(gemm_h_qkv_k,
        cudaFuncAttributeMaxDynamicSharedMemorySize, SMEM_H2);
    cudaFuncSetAttribute(gemm_h_k<false,false,false,true,float>,
        cudaFuncAttributeMaxDynamicSharedMemorySize, SMEM_H2);
    cudaFuncSetAttribute(gemm_h_k<false,true,true,false,float>,
        cudaFuncAttributeMaxDynamicSharedMemorySize, SMEM_H2);
    cudaFuncSetAttribute(gemm_h_k<true,true,false,false,__half>,
        cudaFuncAttributeMaxDynamicSharedMemorySize, SMEM_H2);
    cudaFuncSetAttribute(gemm_h_k<false,false,false,false,float>,
        cudaFuncAttributeMaxDynamicSharedMemorySize, SMEM_H2);

    const long long WSZ = (long long)E_*E_;
    __half* wqT = wh;
    __half* wkT = wh + L_*WSZ;
    __half* wvT = wh + 2*L_*WSZ;
    __half* woT = wh + 3*L_*WSZ;

    // pre-pass: batched transpose + convert weights to half [N][K]
    {
        dim3 gT(E_/32, E_/32, L_);             // (16,16,4)
        transpose_pad_k<<<gT, 256>>>(Wq, wqT, E_, E_, E_, E_, WSZ, WSZ);
        transpose_pad_k<<<gT, 256>>>(Wk, wkT, E_, E_, E_, E_, WSZ, WSZ);
        transpose_pad_k<<<gT, 256>>>(Wv, wvT, E_, E_, E_, E_, WSZ, WSZ);
        transpose_pad_k<<<gT, 256>>>(Wo, woT, E_, E_, E_, E_, WSZ, WSZ);
        dim3 gW1(E_/32, HIDP/32, L_);          // (16,4,4)
        transpose_pad_k<<<gW1, 256>>>(W1, w1h, E_, E_, HID_, HIDP,
                                      (long long)E_*HID_, (long long)HIDP*E_);
        dim3 gW2(HIDP/32, E_/32, L_);          // (4,16,4)
        transpose_pad_k<<<gW2, 256>>>(W2, w2h, HID_, HIDP, E_, E_,
                                      (long long)HID_*E_, (long long)E_*HIDP);
        dim3 gLMt(E_/32, V_/32, 1);            // (16,1000)
        transpose_pad_k<<<gLMt, 256>>>(Wlm, wlmh, E_, E_, V_, V_,
                                       0, 0);
    }

    // embedding
    {
        int n = BT_*E_;
        embed_k<<<(n + 255) / 256, 256>>>(idx, tok, pos, x);
    }

    dim3 gE(E_ / 128, BT_ / 128);               // (4, 32)    proj
    dim3 gQKV(E_ / 128, BT_ / 128, 3);          // (4, 32, 3) fused QKV
    dim3 gLM(V_ / 128, BT_ / 128);              // (250, 32)  lm head
    dim3 gS(T_ / 128, T_ / 128, B_*H_);         // (8, 8, 32) scores
    dim3 gPV(1, T_ / 128, B_*H_);               // (1, 8, 32) PV fp16
    dim3 gVT(T_/32, E_/32, B_);                 // V transpose
    dim3 gM1(HIDP / 128, BT_ / 128);            // (1, 32)    mlp1
    const float scale = 0.125f;                 // 1/sqrt(64)

    for (int l = 0; l < L_; l++) {
        float* attnL = attn + (long long)l * ATTN1;

        layernorm_h_k<<<BT_, 256>>>(x, ln1_g + l*E_, ln1_b + l*E_, hh);

        gemm_h_qkv_k<<<gQKV, 256, SMEM_H2>>>(
            hh, wqT + l*WSZ, wkT + l*WSZ, wvT + l*WSZ, qh, kh, vh);

        transpose_v_k<<<gVT, 256>>>(vh, vth);

        // scores = scale * Q @ K^T
        gemm_h_k<false,false,false,true,float><<<gS, 256, SMEM_H2>>>(
            qh, kh, attnL, HD_, E_, E_, T_,
            H_,
            (long long)T_*E_, (long long)HD_,
            (long long)T_*E_, (long long)HD_,
            (long long)H_*T_*T_, (long long)T_*T_,
            nullptr, 0, nullptr, scale);

        softmax_fused_k<<<dim3(T_, B_*H_), 256>>>(attnL, ph);

        // y = P @ V
        gemm_h_pv_k<<<gPV, 256>>>(ph, vth, yh);

        // x = x + y @ Wo + bo
        gemm_h_k<false,true,true,false,float><<<gE, 256, SMEM_H2>>>(
            yh, woT + l*WSZ, x, E_, E_, E_, E_,
            1, 0,0, 0,0, 0,0, bo + l*E_, E_, x, 1.f);

        layernorm_h_k<<<BT_, 256>>>(x, ln2_g + l*E_, ln2_b + l*E_, hh);

        // m = relu(h @ W1 + b1)   (fp16 tensor path, padded N)
        gemm_h_k<true,true,false,false,__half><<<gM1, 256, SMEM_H2>>>(
            hh, w1h + (long long)l*HIDP*E_, mh, E_, E_, E_, HIDP,
            1, 0,0, 0,0, 0,0, b1 + l*HID_, HID_, nullptr, 1.f);

        // x = x + m @ W2 + b2    (K = HIDP, zero-padded)
        gemm_h_k<false,true,true,false,float><<<gE, 256, SMEM_H2>>>(
            mh, w2h + (long long)l*E_*HIDP, x, HIDP, HIDP, HIDP, E_,
            1, 0,0, 0,0, 0,0, b2 + l*E_, E_, x, 1.f);
    }

    // final LN + LM head
    layernorm_h_k<<<BT_, 256>>>(x, lnf_g, lnf_b, hh);
    gemm_h_k<false,false,false,false,float><<<gLM, 256, SMEM_H2>>>(
        hh, wlmh, logits, E_, E_, E_, V_,
        1, 0,0, 0,0, 0,0, nullptr, 0, nullptr, 1.f);
}